// round 1
// baseline (speedup 1.0000x reference)
#include <cuda_runtime.h>
#include <cuda_bf16.h>
#include <math.h>

// ---------------- problem constants ----------------
#define BB 2
#define SS 2048
#define HH 768
#define NHH 12
#define DD 64
#define LL 4
#define CW 128     // chunk size == window
#define GT 16      // global tokens
#define PP 128     // pairs per batch
#define NLC 3      // output classes
#define FF (4*HH)  // 3072
#define MROWS (BB*SS)  // 4096

// ---------------- scratch (device globals; no allocation allowed) ----------------
__device__ float g_x [MROWS*HH];
__device__ float g_q [MROWS*HH];
__device__ float g_k [MROWS*HH];
__device__ float g_v [MROWS*HH];
__device__ float g_o [MROWS*HH];
__device__ float g_t [MROWS*HH];
__device__ float g_h [MROWS*FF];

// ---------------- embedding gather ----------------
__global__ void embed_kernel(const int* __restrict__ ids,
                             const float* __restrict__ emb,
                             float* __restrict__ x)
{
    int idx = blockIdx.x * blockDim.x + threadIdx.x;
    if (idx >= MROWS * HH) return;
    int tok = idx / HH;
    int d   = idx - tok * HH;
    x[idx] = emb[(long)ids[tok] * HH + d];
}

// ---------------- generic tiled fp32 GEMM: C = epilogue(A[MxK] @ W[KxN] + bias) ----------------
// mode 0: C = scale*(AW+b)
// mode 1: C = AW+b+R   (R has same shape as C)
// mode 2: C = gelu_tanh(AW+b)
#define TM 64
#define TN 64
#define TK 16
__global__ void __launch_bounds__(256)
gemm_kernel(const float* __restrict__ A, const float* __restrict__ W,
            const float* __restrict__ bias, const float* __restrict__ R,
            float* __restrict__ C, int M, int N, int K, float scale, int mode)
{
    __shared__ float As[TK][TM];
    __shared__ float Bs[TK][TN];
    const int tid = threadIdx.x;
    const int tx = tid & 15;
    const int ty = tid >> 4;
    const int row0 = blockIdx.y * TM;
    const int col0 = blockIdx.x * TN;

    // A-load mapping: 256 float4 loads of the 64x16 tile
    const int ar = tid >> 2;        // 0..63  (row within tile)
    const int ak = (tid & 3) * 4;   // 0,4,8,12 (k within tile)
    // W-load mapping: 256 float4 loads of the 16x64 tile
    const int wk = tid >> 4;        // 0..15
    const int wc = (tid & 15) * 4;  // 0..60

    float acc[4][4];
#pragma unroll
    for (int i = 0; i < 4; i++)
#pragma unroll
        for (int j = 0; j < 4; j++) acc[i][j] = 0.f;

    for (int k0 = 0; k0 < K; k0 += TK) {
        float4 a4 = *(const float4*)&A[(long)(row0 + ar) * K + k0 + ak];
        As[ak + 0][ar] = a4.x; As[ak + 1][ar] = a4.y;
        As[ak + 2][ar] = a4.z; As[ak + 3][ar] = a4.w;
        *(float4*)&Bs[wk][wc] = *(const float4*)&W[(long)(k0 + wk) * N + col0 + wc];
        __syncthreads();
#pragma unroll
        for (int kk = 0; kk < TK; kk++) {
            float4 a = *(const float4*)&As[kk][ty * 4];
            float4 b = *(const float4*)&Bs[kk][tx * 4];
            float av[4] = {a.x, a.y, a.z, a.w};
            float bv[4] = {b.x, b.y, b.z, b.w};
#pragma unroll
            for (int i = 0; i < 4; i++)
#pragma unroll
                for (int j = 0; j < 4; j++) acc[i][j] += av[i] * bv[j];
        }
        __syncthreads();
    }

#pragma unroll
    for (int i = 0; i < 4; i++) {
        int r = row0 + ty * 4 + i;
#pragma unroll
        for (int j = 0; j < 4; j++) {
            int c = col0 + tx * 4 + j;
            float val = acc[i][j] + bias[c];
            if (mode == 0) {
                val *= scale;
            } else if (mode == 1) {
                val += R[(long)r * N + c];
            } else {
                float xx = val;
                val = 0.5f * xx * (1.f + tanhf(0.7978845608028654f * (xx + 0.044715f * xx * xx * xx)));
            }
            C[(long)r * N + c] = val;
        }
    }
}

// ---------------- layernorm over H=768 ----------------
__global__ void __launch_bounds__(256)
ln_kernel(const float* __restrict__ in, const float* __restrict__ g,
          const float* __restrict__ b, float* __restrict__ out)
{
    const int row = blockIdx.x;
    const float* x = in + (long)row * HH;
    float v0[3];
    float s = 0.f, s2 = 0.f;
#pragma unroll
    for (int i = 0; i < 3; i++) {
        float t = x[threadIdx.x + i * 256];
        v0[i] = t; s += t; s2 += t * t;
    }
#pragma unroll
    for (int o = 16; o > 0; o >>= 1) {
        s  += __shfl_xor_sync(0xffffffffu, s, o);
        s2 += __shfl_xor_sync(0xffffffffu, s2, o);
    }
    __shared__ float red0[8], red1[8];
    int w = threadIdx.x >> 5;
    if ((threadIdx.x & 31) == 0) { red0[w] = s; red1[w] = s2; }
    __syncthreads();
    if (threadIdx.x < 32) {
        s  = (threadIdx.x < 8) ? red0[threadIdx.x] : 0.f;
        s2 = (threadIdx.x < 8) ? red1[threadIdx.x] : 0.f;
#pragma unroll
        for (int o = 4; o > 0; o >>= 1) {
            s  += __shfl_xor_sync(0xffffffffu, s, o);
            s2 += __shfl_xor_sync(0xffffffffu, s2, o);
        }
        if (threadIdx.x == 0) { red0[0] = s; red1[0] = s2; }
    }
    __syncthreads();
    float mean = red0[0] * (1.f / HH);
    float var  = red1[0] * (1.f / HH) - mean * mean;
    float rstd = rsqrtf(var + 1e-5f);
#pragma unroll
    for (int i = 0; i < 3; i++) {
        int c = threadIdx.x + i * 256;
        out[(long)row * HH + c] = (v0[i] - mean) * rstd * g[c] + b[c];
    }
}

// ---------------- banded attention (one thread per query row, flash-style) ----------------
// grid (NC, NH, B), block 128. Handles the 384 band cols + 16 global cols.
__global__ void __launch_bounds__(128)
band_attn_kernel(const float* __restrict__ q, const float* __restrict__ k,
                 const float* __restrict__ v, float* __restrict__ o)
{
    const int n = blockIdx.x, h = blockIdx.y, b = blockIdx.z;
    const int qi = threadIdx.x;
    const int s_q = n * CW + qi;

    const float* qrow = q + ((long)(b * SS + s_q) * HH + h * DD);
    float qr[DD];
#pragma unroll
    for (int d = 0; d < DD; d++) qr[d] = qrow[d];

    float m = -1e30f, l = 0.f;
    float oa[DD];
#pragma unroll
    for (int d = 0; d < DD; d++) oa[d] = 0.f;

    __shared__ float ks[16][DD];
    __shared__ float vs[16][DD];

    // tiles 0..23: band keys starting at n*CW - CW; tile 24: global keys 0..15
    for (int t = 0; t < 25; t++) {
        const bool is_glob = (t == 24);
        const int p0 = is_glob ? 0 : (n * CW - CW + t * 16);
        __syncthreads();
        for (int f = threadIdx.x; f < 256; f += 128) {
            int j  = f >> 4;
            int d4 = (f & 15) * 4;
            int p  = p0 + j;
            int pc = min(max(p, 0), SS - 1);
            long base = (long)(b * SS + pc) * HH + h * DD + d4;
            *(float4*)&ks[j][d4] = *(const float4*)&k[base];
            *(float4*)&vs[j][d4] = *(const float4*)&v[base];
        }
        __syncthreads();

        float sc[16];
        float tmax = -1e30f;
#pragma unroll
        for (int j = 0; j < 16; j++) {
            int p = p0 + j;
            bool valid = is_glob || ((abs(p - s_q) <= CW) && (p >= GT) && (p < SS));
            float s = -1e30f;
            if (valid) {
                s = 0.f;
#pragma unroll
                for (int d4 = 0; d4 < DD; d4 += 4) {
                    float4 kk = *(const float4*)&ks[j][d4];
                    s += qr[d4] * kk.x + qr[d4 + 1] * kk.y + qr[d4 + 2] * kk.z + qr[d4 + 3] * kk.w;
                }
            }
            sc[j] = s;
            tmax = fmaxf(tmax, s);
        }
        if (tmax > -1e29f) {
            float mnew = fmaxf(m, tmax);
            float alpha = __expf(m - mnew);
            l *= alpha;
#pragma unroll
            for (int d = 0; d < DD; d++) oa[d] *= alpha;
#pragma unroll
            for (int j = 0; j < 16; j++) {
                if (sc[j] > -1e29f) {
                    float pj = __expf(sc[j] - mnew);
                    l += pj;
#pragma unroll
                    for (int d4 = 0; d4 < DD; d4 += 4) {
                        float4 vv = *(const float4*)&vs[j][d4];
                        oa[d4]     += pj * vv.x;
                        oa[d4 + 1] += pj * vv.y;
                        oa[d4 + 2] += pj * vv.z;
                        oa[d4 + 3] += pj * vv.w;
                    }
                }
            }
            m = mnew;
        }
    }
    float inv = 1.f / l;
    float* orow = o + ((long)(b * SS + s_q) * HH + h * DD);
#pragma unroll
    for (int d = 0; d < DD; d++) orow[d] = oa[d] * inv;
}

// ---------------- global-query attention (rows 0..G-1 attend to all S keys) ----------------
// grid (NH, B), block 512 = 16 warps; warp w handles global row g=w. Overwrites o rows < G.
__global__ void __launch_bounds__(512)
glob_attn_kernel(const float* __restrict__ q, const float* __restrict__ k,
                 const float* __restrict__ v, float* __restrict__ o)
{
    const int h = blockIdx.x, b = blockIdx.y;
    const int w = threadIdx.x >> 5, lane = threadIdx.x & 31;
    const int g = w;  // 0..15

    const float* qrow = q + ((long)(b * SS + g) * HH + h * DD);
    float2 qv = *(const float2*)&qrow[lane * 2];
    float m = -1e30f, l = 0.f;
    float2 oacc = make_float2(0.f, 0.f);

    for (int s = 0; s < SS; s++) {
        long base = (long)(b * SS + s) * HH + h * DD + lane * 2;
        float2 kv = *(const float2*)&k[base];
        float part = qv.x * kv.x + qv.y * kv.y;
#pragma unroll
        for (int off = 16; off > 0; off >>= 1)
            part += __shfl_xor_sync(0xffffffffu, part, off);
        float mnew  = fmaxf(m, part);
        float alpha = __expf(m - mnew);
        float e     = __expf(part - mnew);
        l = l * alpha + e;
        float2 vv = *(const float2*)&v[base];
        oacc.x = oacc.x * alpha + e * vv.x;
        oacc.y = oacc.y * alpha + e * vv.y;
        m = mnew;
    }
    float inv = 1.f / l;
    float* orow = o + ((long)(b * SS + g) * HH + h * DD);
    orow[lane * 2]     = oacc.x * inv;
    orow[lane * 2 + 1] = oacc.y * inv;
}

// ---------------- pair gather + classifier head ----------------
// grid B*P = 256 blocks, block 128
__global__ void __launch_bounds__(128)
head_kernel(const float* __restrict__ x, const int* __restrict__ pairs,
            const float* __restrict__ Wh, const float* __restrict__ bh,
            float* __restrict__ out)
{
    const int bp = blockIdx.x;
    const int b = bp >> 7;
    const int i = pairs[bp * 2 + 0];
    const int j = pairs[bp * 2 + 1];
    const float* xi = x + (long)(b * SS + i) * HH;
    const float* xj = x + (long)(b * SS + j) * HH;

    float acc[NLC] = {0.f, 0.f, 0.f};
    for (int d = threadIdx.x; d < 2 * HH; d += 128) {
        float e = (d < HH) ? xi[d] : xj[d - HH];
        acc[0] += e * Wh[d * NLC + 0];
        acc[1] += e * Wh[d * NLC + 1];
        acc[2] += e * Wh[d * NLC + 2];
    }
#pragma unroll
    for (int o = 16; o > 0; o >>= 1) {
#pragma unroll
        for (int c = 0; c < NLC; c++)
            acc[c] += __shfl_xor_sync(0xffffffffu, acc[c], o);
    }
    __shared__ float sm[NLC][4];
    int w = threadIdx.x >> 5;
    if ((threadIdx.x & 31) == 0) {
#pragma unroll
        for (int c = 0; c < NLC; c++) sm[c][w] = acc[c];
    }
    __syncthreads();
    if (threadIdx.x < NLC) {
        float s = sm[threadIdx.x][0] + sm[threadIdx.x][1] + sm[threadIdx.x][2] + sm[threadIdx.x][3];
        out[bp * NLC + threadIdx.x] = s + bh[threadIdx.x];
    }
}

// ---------------- host orchestration ----------------
extern "C" void kernel_launch(void* const* d_in, const int* in_sizes, int n_in,
                              void* d_out, int out_size)
{
    const int*   input_ids    = (const int*)  d_in[0];
    const int*   pair_indices = (const int*)  d_in[1];
    const float* emb          = (const float*)d_in[2];
    const float* Wq  = (const float*)d_in[3];
    const float* bq  = (const float*)d_in[4];
    const float* Wk  = (const float*)d_in[5];
    const float* bk  = (const float*)d_in[6];
    const float* Wv  = (const float*)d_in[7];
    const float* bv  = (const float*)d_in[8];
    const float* Wo  = (const float*)d_in[9];
    const float* bo  = (const float*)d_in[10];
    const float* ln1g = (const float*)d_in[11];
    const float* ln1b = (const float*)d_in[12];
    const float* Wf1 = (const float*)d_in[13];
    const float* bf1 = (const float*)d_in[14];
    const float* Wf2 = (const float*)d_in[15];
    const float* bf2 = (const float*)d_in[16];
    const float* ln2g = (const float*)d_in[17];
    const float* ln2b = (const float*)d_in[18];
    const float* Wh  = (const float*)d_in[19];
    const float* bh  = (const float*)d_in[20];
    float* out = (float*)d_out;

    float *x, *qb, *kb, *vb, *ob, *tb, *hb;
    cudaGetSymbolAddress((void**)&x,  g_x);
    cudaGetSymbolAddress((void**)&qb, g_q);
    cudaGetSymbolAddress((void**)&kb, g_k);
    cudaGetSymbolAddress((void**)&vb, g_v);
    cudaGetSymbolAddress((void**)&ob, g_o);
    cudaGetSymbolAddress((void**)&tb, g_t);
    cudaGetSymbolAddress((void**)&hb, g_h);

    // 1. embedding
    {
        int total = MROWS * HH;
        embed_kernel<<<(total + 255) / 256, 256>>>(input_ids, emb, x);
    }

    const dim3 gemmHH((HH / TN), (MROWS / TM));   // N=768
    const dim3 gemmFF((FF / TN), (MROWS / TM));   // N=3072
    const dim3 attnGrid(SS / CW, NHH, BB);
    const dim3 globGrid(NHH, BB);

    for (int l = 0; l < LL; l++) {
        const float* wq = Wq  + (long)l * HH * HH;
        const float* wk = Wk  + (long)l * HH * HH;
        const float* wv = Wv  + (long)l * HH * HH;
        const float* wo = Wo  + (long)l * HH * HH;
        const float* w1 = Wf1 + (long)l * HH * FF;
        const float* w2 = Wf2 + (long)l * FF * HH;

        // q/k/v projections
        gemm_kernel<<<gemmHH, 256>>>(x, wq, bq + l * HH, nullptr, qb, MROWS, HH, HH, 0.125f, 0);
        gemm_kernel<<<gemmHH, 256>>>(x, wk, bk + l * HH, nullptr, kb, MROWS, HH, HH, 1.0f,   0);
        gemm_kernel<<<gemmHH, 256>>>(x, wv, bv + l * HH, nullptr, vb, MROWS, HH, HH, 1.0f,   0);

        // attention: band for all rows, then overwrite rows < G with full global attention
        band_attn_kernel<<<attnGrid, 128>>>(qb, kb, vb, ob);
        glob_attn_kernel<<<globGrid, 512>>>(qb, kb, vb, ob);

        // output projection + residual, then LN1
        gemm_kernel<<<gemmHH, 256>>>(ob, wo, bo + l * HH, x, tb, MROWS, HH, HH, 1.0f, 1);
        ln_kernel<<<MROWS, 256>>>(tb, ln1g + l * HH, ln1b + l * HH, x);

        // FFN: gelu(x@Wf1+b), then @Wf2+b + residual, LN2
        gemm_kernel<<<gemmFF, 256>>>(x, w1, bf1 + l * FF, nullptr, hb, MROWS, FF, HH, 1.0f, 2);
        gemm_kernel<<<gemmHH, 256>>>(hb, w2, bf2 + l * HH, x, tb, MROWS, HH, FF, 1.0f, 1);
        ln_kernel<<<MROWS, 256>>>(tb, ln2g + l * HH, ln2b + l * HH, x);
    }

    // pair gather + head
    head_kernel<<<BB * PP, 128>>>(x, pair_indices, Wh, bh, out);
}

// round 2
// speedup vs baseline: 1.1881x; 1.1881x over previous
#include <cuda_runtime.h>
#include <cuda_bf16.h>
#include <math.h>

// ---------------- problem constants ----------------
#define BB 2
#define SS 2048
#define HH 768
#define NHH 12
#define DD 64
#define LL 4
#define CW 128     // chunk size == window
#define GT 16      // global tokens
#define PP 128     // pairs per batch
#define NLC 3      // output classes
#define FF (4*HH)  // 3072
#define MROWS (BB*SS)  // 4096

// ---------------- scratch (device globals; no allocation allowed) ----------------
__device__ float g_x [MROWS*HH];
__device__ float g_q [MROWS*HH];
__device__ float g_k [MROWS*HH];
__device__ float g_v [MROWS*HH];
__device__ float g_o [MROWS*HH];
__device__ float g_t [MROWS*HH];
__device__ float g_h [MROWS*FF];

// ---------------- embedding gather ----------------
__global__ void embed_kernel(const int* __restrict__ ids,
                             const float* __restrict__ emb,
                             float* __restrict__ x)
{
    int idx = blockIdx.x * blockDim.x + threadIdx.x;
    if (idx >= MROWS * HH) return;
    int tok = idx / HH;
    int d   = idx - tok * HH;
    x[idx] = emb[(long)ids[tok] * HH + d];
}

// ---------------- tiled fp32 GEMM: C = epilogue(A[MxK] @ W[KxN] + bias) ----------------
// TM=128, TN=64, TK=16, 256 threads, 8x4 microtile, double-buffered smem.
// mode 0: C = scale*(AW+b)
// mode 1: C = AW+b+R
// mode 2: C = gelu_tanh(AW+b)
#define TM 128
#define TN 64
#define TK 16
__global__ void __launch_bounds__(256)
gemm_kernel(const float* __restrict__ A, const float* __restrict__ W,
            const float* __restrict__ bias, const float* __restrict__ R,
            float* __restrict__ C, int M, int N, int K, float scale, int mode)
{
    __shared__ float As[2][TK][TM];   // 16 KB
    __shared__ float Bs[2][TK][TN];   // 8 KB

    const int tid  = threadIdx.x;
    const int tx   = tid & 15;        // col group 0..15 -> cols tx*4
    const int ty   = tid >> 4;        // row group 0..15 -> rows ty*8
    const int row0 = blockIdx.y * TM;
    const int col0 = blockIdx.x * TN;

    // A-tile load mapping (128x16 floats = 512 float4; 2 per thread)
    const int arow = tid >> 1;            // 0..127
    const int akk  = (tid & 1) * 8;       // 0 or 8
    // B-tile load mapping (16x64 floats = 256 float4; 1 per thread)
    const int bk   = tid >> 4;            // 0..15
    const int bc   = (tid & 15) * 4;      // 0..60

    const int nk = K / TK;

    float acc[8][4];
#pragma unroll
    for (int i = 0; i < 8; i++)
#pragma unroll
        for (int j = 0; j < 4; j++) acc[i][j] = 0.f;

    // prologue: load tile 0
    {
        float4 ra0 = *(const float4*)&A[(long)(row0 + arow) * K + akk + 0];
        float4 ra1 = *(const float4*)&A[(long)(row0 + arow) * K + akk + 4];
        float4 rb  = *(const float4*)&W[(long)bk * N + col0 + bc];
        As[0][akk + 0][arow] = ra0.x; As[0][akk + 1][arow] = ra0.y;
        As[0][akk + 2][arow] = ra0.z; As[0][akk + 3][arow] = ra0.w;
        As[0][akk + 4][arow] = ra1.x; As[0][akk + 5][arow] = ra1.y;
        As[0][akk + 6][arow] = ra1.z; As[0][akk + 7][arow] = ra1.w;
        *(float4*)&Bs[0][bk][bc] = rb;
    }
    __syncthreads();

    for (int kt = 0; kt < nk; kt++) {
        const int c = kt & 1;
        float4 ra0, ra1, rb;
        const bool more = (kt + 1 < nk);
        if (more) {
            int k0 = (kt + 1) * TK;
            ra0 = *(const float4*)&A[(long)(row0 + arow) * K + k0 + akk + 0];
            ra1 = *(const float4*)&A[(long)(row0 + arow) * K + k0 + akk + 4];
            rb  = *(const float4*)&W[(long)(k0 + bk) * N + col0 + bc];
        }

#pragma unroll
        for (int kk = 0; kk < TK; kk++) {
            float4 a0 = *(const float4*)&As[c][kk][ty * 8];
            float4 a1 = *(const float4*)&As[c][kk][ty * 8 + 4];
            float4 b  = *(const float4*)&Bs[c][kk][tx * 4];
            float av[8] = {a0.x, a0.y, a0.z, a0.w, a1.x, a1.y, a1.z, a1.w};
            float bv[4] = {b.x, b.y, b.z, b.w};
#pragma unroll
            for (int i = 0; i < 8; i++)
#pragma unroll
                for (int j = 0; j < 4; j++) acc[i][j] += av[i] * bv[j];
        }

        if (more) {
            const int n = c ^ 1;
            As[n][akk + 0][arow] = ra0.x; As[n][akk + 1][arow] = ra0.y;
            As[n][akk + 2][arow] = ra0.z; As[n][akk + 3][arow] = ra0.w;
            As[n][akk + 4][arow] = ra1.x; As[n][akk + 5][arow] = ra1.y;
            As[n][akk + 6][arow] = ra1.z; As[n][akk + 7][arow] = ra1.w;
            *(float4*)&Bs[n][bk][bc] = rb;
            __syncthreads();
        }
    }

    // epilogue: rows ty*8+i, cols col0 + tx*4 .. +3 (float4 per row)
    const int ccol = col0 + tx * 4;
    float4 bv4 = *(const float4*)&bias[ccol];
#pragma unroll
    for (int i = 0; i < 8; i++) {
        int r = row0 + ty * 8 + i;
        float4 val;
        val.x = acc[i][0] + bv4.x;
        val.y = acc[i][1] + bv4.y;
        val.z = acc[i][2] + bv4.z;
        val.w = acc[i][3] + bv4.w;
        if (mode == 0) {
            val.x *= scale; val.y *= scale; val.z *= scale; val.w *= scale;
        } else if (mode == 1) {
            float4 rr = *(const float4*)&R[(long)r * N + ccol];
            val.x += rr.x; val.y += rr.y; val.z += rr.z; val.w += rr.w;
        } else {
            float t[4] = {val.x, val.y, val.z, val.w};
#pragma unroll
            for (int u = 0; u < 4; u++) {
                float xx = t[u];
                t[u] = 0.5f * xx * (1.f + tanhf(0.7978845608028654f * (xx + 0.044715f * xx * xx * xx)));
            }
            val.x = t[0]; val.y = t[1]; val.z = t[2]; val.w = t[3];
        }
        *(float4*)&C[(long)r * N + ccol] = val;
    }
}

// ---------------- layernorm over H=768 ----------------
__global__ void __launch_bounds__(256)
ln_kernel(const float* __restrict__ in, const float* __restrict__ g,
          const float* __restrict__ b, float* __restrict__ out)
{
    const int row = blockIdx.x;
    const float* x = in + (long)row * HH;
    float v0[3];
    float s = 0.f, s2 = 0.f;
#pragma unroll
    for (int i = 0; i < 3; i++) {
        float t = x[threadIdx.x + i * 256];
        v0[i] = t; s += t; s2 += t * t;
    }
#pragma unroll
    for (int o = 16; o > 0; o >>= 1) {
        s  += __shfl_xor_sync(0xffffffffu, s, o);
        s2 += __shfl_xor_sync(0xffffffffu, s2, o);
    }
    __shared__ float red0[8], red1[8];
    int w = threadIdx.x >> 5;
    if ((threadIdx.x & 31) == 0) { red0[w] = s; red1[w] = s2; }
    __syncthreads();
    if (threadIdx.x < 32) {
        s  = (threadIdx.x < 8) ? red0[threadIdx.x] : 0.f;
        s2 = (threadIdx.x < 8) ? red1[threadIdx.x] : 0.f;
#pragma unroll
        for (int o = 4; o > 0; o >>= 1) {
            s  += __shfl_xor_sync(0xffffffffu, s, o);
            s2 += __shfl_xor_sync(0xffffffffu, s2, o);
        }
        if (threadIdx.x == 0) { red0[0] = s; red1[0] = s2; }
    }
    __syncthreads();
    float mean = red0[0] * (1.f / HH);
    float var  = red1[0] * (1.f / HH) - mean * mean;
    float rstd = rsqrtf(var + 1e-5f);
#pragma unroll
    for (int i = 0; i < 3; i++) {
        int c = threadIdx.x + i * 256;
        out[(long)row * HH + c] = (v0[i] - mean) * rstd * g[c] + b[c];
    }
}

// ---------------- banded attention (one thread per query row, flash-style) ----------------
__global__ void __launch_bounds__(128)
band_attn_kernel(const float* __restrict__ q, const float* __restrict__ k,
                 const float* __restrict__ v, float* __restrict__ o)
{
    const int n = blockIdx.x, h = blockIdx.y, b = blockIdx.z;
    const int qi = threadIdx.x;
    const int s_q = n * CW + qi;

    const float* qrow = q + ((long)(b * SS + s_q) * HH + h * DD);
    float qr[DD];
#pragma unroll
    for (int d = 0; d < DD; d++) qr[d] = qrow[d];

    float m = -1e30f, l = 0.f;
    float oa[DD];
#pragma unroll
    for (int d = 0; d < DD; d++) oa[d] = 0.f;

    __shared__ float ks[16][DD];
    __shared__ float vs[16][DD];

    for (int t = 0; t < 25; t++) {
        const bool is_glob = (t == 24);
        const int p0 = is_glob ? 0 : (n * CW - CW + t * 16);
        __syncthreads();
        for (int f = threadIdx.x; f < 256; f += 128) {
            int j  = f >> 4;
            int d4 = (f & 15) * 4;
            int p  = p0 + j;
            int pc = min(max(p, 0), SS - 1);
            long base = (long)(b * SS + pc) * HH + h * DD + d4;
            *(float4*)&ks[j][d4] = *(const float4*)&k[base];
            *(float4*)&vs[j][d4] = *(const float4*)&v[base];
        }
        __syncthreads();

        float sc[16];
        float tmax = -1e30f;
#pragma unroll
        for (int j = 0; j < 16; j++) {
            int p = p0 + j;
            bool valid = is_glob || ((abs(p - s_q) <= CW) && (p >= GT) && (p < SS));
            float s = -1e30f;
            if (valid) {
                s = 0.f;
#pragma unroll
                for (int d4 = 0; d4 < DD; d4 += 4) {
                    float4 kk = *(const float4*)&ks[j][d4];
                    s += qr[d4] * kk.x + qr[d4 + 1] * kk.y + qr[d4 + 2] * kk.z + qr[d4 + 3] * kk.w;
                }
            }
            sc[j] = s;
            tmax = fmaxf(tmax, s);
        }
        if (tmax > -1e29f) {
            float mnew = fmaxf(m, tmax);
            float alpha = __expf(m - mnew);
            l *= alpha;
#pragma unroll
            for (int d = 0; d < DD; d++) oa[d] *= alpha;
#pragma unroll
            for (int j = 0; j < 16; j++) {
                if (sc[j] > -1e29f) {
                    float pj = __expf(sc[j] - mnew);
                    l += pj;
#pragma unroll
                    for (int d4 = 0; d4 < DD; d4 += 4) {
                        float4 vv = *(const float4*)&vs[j][d4];
                        oa[d4]     += pj * vv.x;
                        oa[d4 + 1] += pj * vv.y;
                        oa[d4 + 2] += pj * vv.z;
                        oa[d4 + 3] += pj * vv.w;
                    }
                }
            }
            m = mnew;
        }
    }
    float inv = 1.f / l;
    float* orow = o + ((long)(b * SS + s_q) * HH + h * DD);
#pragma unroll
    for (int d = 0; d < DD; d++) orow[d] = oa[d] * inv;
}

// ---------------- global-query attention (rows 0..G-1 attend to all S keys) ----------------
__global__ void __launch_bounds__(512)
glob_attn_kernel(const float* __restrict__ q, const float* __restrict__ k,
                 const float* __restrict__ v, float* __restrict__ o)
{
    const int h = blockIdx.x, b = blockIdx.y;
    const int w = threadIdx.x >> 5, lane = threadIdx.x & 31;
    const int g = w;  // 0..15

    const float* qrow = q + ((long)(b * SS + g) * HH + h * DD);
    float2 qv = *(const float2*)&qrow[lane * 2];
    float m = -1e30f, l = 0.f;
    float2 oacc = make_float2(0.f, 0.f);

    for (int s = 0; s < SS; s++) {
        long base = (long)(b * SS + s) * HH + h * DD + lane * 2;
        float2 kv = *(const float2*)&k[base];
        float part = qv.x * kv.x + qv.y * kv.y;
#pragma unroll
        for (int off = 16; off > 0; off >>= 1)
            part += __shfl_xor_sync(0xffffffffu, part, off);
        float mnew  = fmaxf(m, part);
        float alpha = __expf(m - mnew);
        float e     = __expf(part - mnew);
        l = l * alpha + e;
        float2 vv = *(const float2*)&v[base];
        oacc.x = oacc.x * alpha + e * vv.x;
        oacc.y = oacc.y * alpha + e * vv.y;
        m = mnew;
    }
    float inv = 1.f / l;
    float* orow = o + ((long)(b * SS + g) * HH + h * DD);
    orow[lane * 2]     = oacc.x * inv;
    orow[lane * 2 + 1] = oacc.y * inv;
}

// ---------------- pair gather + classifier head ----------------
__global__ void __launch_bounds__(128)
head_kernel(const float* __restrict__ x, const int* __restrict__ pairs,
            const float* __restrict__ Wh, const float* __restrict__ bh,
            float* __restrict__ out)
{
    const int bp = blockIdx.x;
    const int b = bp >> 7;
    const int i = pairs[bp * 2 + 0];
    const int j = pairs[bp * 2 + 1];
    const float* xi = x + (long)(b * SS + i) * HH;
    const float* xj = x + (long)(b * SS + j) * HH;

    float acc[NLC] = {0.f, 0.f, 0.f};
    for (int d = threadIdx.x; d < 2 * HH; d += 128) {
        float e = (d < HH) ? xi[d] : xj[d - HH];
        acc[0] += e * Wh[d * NLC + 0];
        acc[1] += e * Wh[d * NLC + 1];
        acc[2] += e * Wh[d * NLC + 2];
    }
#pragma unroll
    for (int o = 16; o > 0; o >>= 1) {
#pragma unroll
        for (int c = 0; c < NLC; c++)
            acc[c] += __shfl_xor_sync(0xffffffffu, acc[c], o);
    }
    __shared__ float sm[NLC][4];
    int w = threadIdx.x >> 5;
    if ((threadIdx.x & 31) == 0) {
#pragma unroll
        for (int c = 0; c < NLC; c++) sm[c][w] = acc[c];
    }
    __syncthreads();
    if (threadIdx.x < NLC) {
        float s = sm[threadIdx.x][0] + sm[threadIdx.x][1] + sm[threadIdx.x][2] + sm[threadIdx.x][3];
        out[bp * NLC + threadIdx.x] = s + bh[threadIdx.x];
    }
}

// ---------------- host orchestration ----------------
extern "C" void kernel_launch(void* const* d_in, const int* in_sizes, int n_in,
                              void* d_out, int out_size)
{
    const int*   input_ids    = (const int*)  d_in[0];
    const int*   pair_indices = (const int*)  d_in[1];
    const float* emb          = (const float*)d_in[2];
    const float* Wq  = (const float*)d_in[3];
    const float* bq  = (const float*)d_in[4];
    const float* Wk  = (const float*)d_in[5];
    const float* bk  = (const float*)d_in[6];
    const float* Wv  = (const float*)d_in[7];
    const float* bv  = (const float*)d_in[8];
    const float* Wo  = (const float*)d_in[9];
    const float* bo  = (const float*)d_in[10];
    const float* ln1g = (const float*)d_in[11];
    const float* ln1b = (const float*)d_in[12];
    const float* Wf1 = (const float*)d_in[13];
    const float* bf1 = (const float*)d_in[14];
    const float* Wf2 = (const float*)d_in[15];
    const float* bf2 = (const float*)d_in[16];
    const float* ln2g = (const float*)d_in[17];
    const float* ln2b = (const float*)d_in[18];
    const float* Wh  = (const float*)d_in[19];
    const float* bh  = (const float*)d_in[20];
    float* out = (float*)d_out;

    float *x, *qb, *kb, *vb, *ob, *tb, *hb;
    cudaGetSymbolAddress((void**)&x,  g_x);
    cudaGetSymbolAddress((void**)&qb, g_q);
    cudaGetSymbolAddress((void**)&kb, g_k);
    cudaGetSymbolAddress((void**)&vb, g_v);
    cudaGetSymbolAddress((void**)&ob, g_o);
    cudaGetSymbolAddress((void**)&tb, g_t);
    cudaGetSymbolAddress((void**)&hb, g_h);

    // 1. embedding
    {
        int total = MROWS * HH;
        embed_kernel<<<(total + 255) / 256, 256>>>(input_ids, emb, x);
    }

    const dim3 gemmHH((HH / TN), (MROWS / TM));   // 12 x 32
    const dim3 gemmFF((FF / TN), (MROWS / TM));   // 48 x 32
    const dim3 attnGrid(SS / CW, NHH, BB);
    const dim3 globGrid(NHH, BB);

    for (int l = 0; l < LL; l++) {
        const float* wq = Wq  + (long)l * HH * HH;
        const float* wk = Wk  + (long)l * HH * HH;
        const float* wv = Wv  + (long)l * HH * HH;
        const float* wo = Wo  + (long)l * HH * HH;
        const float* w1 = Wf1 + (long)l * HH * FF;
        const float* w2 = Wf2 + (long)l * FF * HH;

        // q/k/v projections
        gemm_kernel<<<gemmHH, 256>>>(x, wq, bq + l * HH, nullptr, qb, MROWS, HH, HH, 0.125f, 0);
        gemm_kernel<<<gemmHH, 256>>>(x, wk, bk + l * HH, nullptr, kb, MROWS, HH, HH, 1.0f,   0);
        gemm_kernel<<<gemmHH, 256>>>(x, wv, bv + l * HH, nullptr, vb, MROWS, HH, HH, 1.0f,   0);

        // attention: band for all rows, then overwrite rows < G with full global attention
        band_attn_kernel<<<attnGrid, 128>>>(qb, kb, vb, ob);
        glob_attn_kernel<<<globGrid, 512>>>(qb, kb, vb, ob);

        // output projection + residual, then LN1
        gemm_kernel<<<gemmHH, 256>>>(ob, wo, bo + l * HH, x, tb, MROWS, HH, HH, 1.0f, 1);
        ln_kernel<<<MROWS, 256>>>(tb, ln1g + l * HH, ln1b + l * HH, x);

        // FFN: gelu(x@Wf1+b), then @Wf2+b + residual, LN2
        gemm_kernel<<<gemmFF, 256>>>(x, w1, bf1 + l * FF, nullptr, hb, MROWS, FF, HH, 1.0f, 2);
        gemm_kernel<<<gemmHH, 256>>>(hb, w2, bf2 + l * HH, x, tb, MROWS, HH, FF, 1.0f, 1);
        ln_kernel<<<MROWS, 256>>>(tb, ln2g + l * HH, ln2b + l * HH, x);
    }

    // pair gather + head
    head_kernel<<<BB * PP, 128>>>(x, pair_indices, Wh, bh, out);
}

// round 3
// speedup vs baseline: 1.7222x; 1.4495x over previous
#include <cuda_runtime.h>
#include <cuda_bf16.h>
#include <math.h>

// ---------------- problem constants ----------------
#define BB 2
#define SS 2048
#define HH 768
#define NHH 12
#define DD 64
#define LL 4
#define CW 128
#define GT 16
#define PP 128
#define NLC 3
#define FF (4*HH)
#define MROWS (BB*SS)

// ---------------- scratch ----------------
__device__ float g_x [MROWS*HH];
__device__ float g_q [MROWS*HH];
__device__ float g_k [MROWS*HH];
__device__ float g_v [MROWS*HH];
__device__ float g_o [MROWS*HH];
__device__ float g_t [MROWS*HH];
__device__ float g_h [MROWS*FF];

// ---------------- embedding gather ----------------
__global__ void embed_kernel(const int* __restrict__ ids,
                             const float* __restrict__ emb,
                             float* __restrict__ x)
{
    int idx = blockIdx.x * blockDim.x + threadIdx.x;
    if (idx >= MROWS * HH) return;
    int tok = idx / HH;
    int d   = idx - tok * HH;
    x[idx] = emb[(long)ids[tok] * HH + d];
}

// ---------------- tf32 tensor-core GEMM ----------------
// C[M,N] = epilogue(A[M,K] @ W[K,N] + bias)
// CTA 128x64, 4 warps (each 32x64), TK=16 double-buffered.
// mode 0: scale*(AW+b); mode 1: AW+b+R; mode 2: gelu(AW+b)
#define GM 128
#define GN 64
#define GK 16
#define MPAD 132
#define NPAD 68

__device__ __forceinline__ unsigned f2tf(float x) {
    unsigned r;
    asm("cvt.rna.tf32.f32 %0, %1;" : "=r"(r) : "f"(x));
    return r;
}

__device__ __forceinline__ void mma_tf32(float* d, const unsigned* a, const unsigned* b) {
    asm volatile(
        "mma.sync.aligned.m16n8k8.row.col.f32.tf32.tf32.f32 "
        "{%0,%1,%2,%3}, {%4,%5,%6,%7}, {%8,%9}, {%0,%1,%2,%3};\n"
        : "+f"(d[0]), "+f"(d[1]), "+f"(d[2]), "+f"(d[3])
        : "r"(a[0]), "r"(a[1]), "r"(a[2]), "r"(a[3]),
          "r"(b[0]), "r"(b[1]));
}

__global__ void __launch_bounds__(128)
gemm_kernel(const float* __restrict__ A, const float* __restrict__ W,
            const float* __restrict__ bias, const float* __restrict__ R,
            float* __restrict__ C, int M, int N, int K, float scale, int mode)
{
    __shared__ float As[2][GK][MPAD];  // A tile, [k][m] padded: frag reads conflict-free
    __shared__ float Bs[2][GK][NPAD];  // B tile, [k][n] padded

    const int tid  = threadIdx.x;
    const int w    = tid >> 5;
    const int lane = tid & 31;
    const int gid  = lane >> 2;   // groupID 0..7
    const int tig  = lane & 3;    // thread in group 0..3
    const int row0 = blockIdx.y * GM;
    const int col0 = blockIdx.x * GN;

    // A staging: thread -> row tid, 4 float4 over k (16)
    // B staging: kk = tid>>3 (0..15), nn = (tid&7)*8 : 2 float4
    const int bkk = tid >> 3;
    const int bnn = (tid & 7) * 8;

    float acc[2][8][4];
#pragma unroll
    for (int mt = 0; mt < 2; mt++)
#pragma unroll
        for (int nt = 0; nt < 8; nt++)
#pragma unroll
            for (int u = 0; u < 4; u++) acc[mt][nt][u] = 0.f;

    const int nk = K / GK;

    // prologue: stage tile 0
    {
        const float* arow = &A[(long)(row0 + tid) * K];
#pragma unroll
        for (int j = 0; j < 4; j++) {
            float4 v = *(const float4*)&arow[4 * j];
            As[0][4 * j + 0][tid] = __uint_as_float(f2tf(v.x));
            As[0][4 * j + 1][tid] = __uint_as_float(f2tf(v.y));
            As[0][4 * j + 2][tid] = __uint_as_float(f2tf(v.z));
            As[0][4 * j + 3][tid] = __uint_as_float(f2tf(v.w));
        }
#pragma unroll
        for (int j = 0; j < 2; j++) {
            float4 v = *(const float4*)&W[(long)bkk * N + col0 + bnn + 4 * j];
            float4 t;
            t.x = __uint_as_float(f2tf(v.x));
            t.y = __uint_as_float(f2tf(v.y));
            t.z = __uint_as_float(f2tf(v.z));
            t.w = __uint_as_float(f2tf(v.w));
            *(float4*)&Bs[0][bkk][bnn + 4 * j] = t;
        }
    }
    __syncthreads();

    for (int kt = 0; kt < nk; kt++) {
        const int buf = kt & 1;
        const bool more = (kt + 1 < nk);
        float4 ra[4], rb[2];
        if (more) {
            int k0 = (kt + 1) * GK;
            const float* arow = &A[(long)(row0 + tid) * K + k0];
#pragma unroll
            for (int j = 0; j < 4; j++) ra[j] = *(const float4*)&arow[4 * j];
#pragma unroll
            for (int j = 0; j < 2; j++)
                rb[j] = *(const float4*)&W[(long)(k0 + bkk) * N + col0 + bnn + 4 * j];
        }

        // compute: 2 k8-steps
#pragma unroll
        for (int kq = 0; kq < 2; kq++) {
            const int k8 = kq * 8;
            unsigned afr[2][4];
#pragma unroll
            for (int mt = 0; mt < 2; mt++) {
                int m = w * 32 + mt * 16 + gid;
                afr[mt][0] = __float_as_uint(As[buf][k8 + tig    ][m]);
                afr[mt][1] = __float_as_uint(As[buf][k8 + tig    ][m + 8]);
                afr[mt][2] = __float_as_uint(As[buf][k8 + tig + 4][m]);
                afr[mt][3] = __float_as_uint(As[buf][k8 + tig + 4][m + 8]);
            }
            unsigned bfr[8][2];
#pragma unroll
            for (int nt = 0; nt < 8; nt++) {
                int n = nt * 8 + gid;
                bfr[nt][0] = __float_as_uint(Bs[buf][k8 + tig    ][n]);
                bfr[nt][1] = __float_as_uint(Bs[buf][k8 + tig + 4][n]);
            }
#pragma unroll
            for (int mt = 0; mt < 2; mt++)
#pragma unroll
                for (int nt = 0; nt < 8; nt++)
                    mma_tf32(acc[mt][nt], afr[mt], bfr[nt]);
        }

        if (more) {
            const int nb = buf ^ 1;
#pragma unroll
            for (int j = 0; j < 4; j++) {
                As[nb][4 * j + 0][tid] = __uint_as_float(f2tf(ra[j].x));
                As[nb][4 * j + 1][tid] = __uint_as_float(f2tf(ra[j].y));
                As[nb][4 * j + 2][tid] = __uint_as_float(f2tf(ra[j].z));
                As[nb][4 * j + 3][tid] = __uint_as_float(f2tf(ra[j].w));
            }
#pragma unroll
            for (int j = 0; j < 2; j++) {
                float4 t;
                t.x = __uint_as_float(f2tf(rb[j].x));
                t.y = __uint_as_float(f2tf(rb[j].y));
                t.z = __uint_as_float(f2tf(rb[j].z));
                t.w = __uint_as_float(f2tf(rb[j].w));
                *(float4*)&Bs[nb][bkk][bnn + 4 * j] = t;
            }
            __syncthreads();
        }
    }

    // ---------------- epilogue ----------------
    // acc[mt][nt]: rows row0 + w*32 + mt*16 + gid (+8), cols col0 + nt*8 + 2*tig (+1)
#pragma unroll
    for (int nt = 0; nt < 8; nt++) {
        const int cc = col0 + nt * 8 + 2 * tig;
        float2 bv = *(const float2*)&bias[cc];
#pragma unroll
        for (int mt = 0; mt < 2; mt++) {
            int r0 = row0 + w * 32 + mt * 16 + gid;
#pragma unroll
            for (int half = 0; half < 2; half++) {
                int rr = r0 + half * 8;
                float vx = acc[mt][nt][half * 2 + 0] + bv.x;
                float vy = acc[mt][nt][half * 2 + 1] + bv.y;
                if (mode == 0) {
                    vx *= scale; vy *= scale;
                } else if (mode == 1) {
                    float2 rrv = *(const float2*)&R[(long)rr * N + cc];
                    vx += rrv.x; vy += rrv.y;
                } else {
                    float t0 = vx, t1 = vy;
                    vx = 0.5f * t0 * (1.f + tanhf(0.7978845608028654f * (t0 + 0.044715f * t0 * t0 * t0)));
                    vy = 0.5f * t1 * (1.f + tanhf(0.7978845608028654f * (t1 + 0.044715f * t1 * t1 * t1)));
                }
                float2 outv = make_float2(vx, vy);
                *(float2*)&C[(long)rr * N + cc] = outv;
            }
        }
    }
}

// ---------------- layernorm over H=768 ----------------
__global__ void __launch_bounds__(256)
ln_kernel(const float* __restrict__ in, const float* __restrict__ g,
          const float* __restrict__ b, float* __restrict__ out)
{
    const int row = blockIdx.x;
    const float* x = in + (long)row * HH;
    float v0[3];
    float s = 0.f, s2 = 0.f;
#pragma unroll
    for (int i = 0; i < 3; i++) {
        float t = x[threadIdx.x + i * 256];
        v0[i] = t; s += t; s2 += t * t;
    }
#pragma unroll
    for (int o = 16; o > 0; o >>= 1) {
        s  += __shfl_xor_sync(0xffffffffu, s, o);
        s2 += __shfl_xor_sync(0xffffffffu, s2, o);
    }
    __shared__ float red0[8], red1[8];
    int w = threadIdx.x >> 5;
    if ((threadIdx.x & 31) == 0) { red0[w] = s; red1[w] = s2; }
    __syncthreads();
    if (threadIdx.x < 32) {
        s  = (threadIdx.x < 8) ? red0[threadIdx.x] : 0.f;
        s2 = (threadIdx.x < 8) ? red1[threadIdx.x] : 0.f;
#pragma unroll
        for (int o = 4; o > 0; o >>= 1) {
            s  += __shfl_xor_sync(0xffffffffu, s, o);
            s2 += __shfl_xor_sync(0xffffffffu, s2, o);
        }
        if (threadIdx.x == 0) { red0[0] = s; red1[0] = s2; }
    }
    __syncthreads();
    float mean = red0[0] * (1.f / HH);
    float var  = red1[0] * (1.f / HH) - mean * mean;
    float rstd = rsqrtf(var + 1e-5f);
#pragma unroll
    for (int i = 0; i < 3; i++) {
        int c = threadIdx.x + i * 256;
        out[(long)row * HH + c] = (v0[i] - mean) * rstd * g[c] + b[c];
    }
}

// ---------------- banded attention ----------------
__global__ void __launch_bounds__(128)
band_attn_kernel(const float* __restrict__ q, const float* __restrict__ k,
                 const float* __restrict__ v, float* __restrict__ o)
{
    const int n = blockIdx.x, h = blockIdx.y, b = blockIdx.z;
    const int qi = threadIdx.x;
    const int s_q = n * CW + qi;

    const float* qrow = q + ((long)(b * SS + s_q) * HH + h * DD);
    float qr[DD];
#pragma unroll
    for (int d = 0; d < DD; d++) qr[d] = qrow[d];

    float m = -1e30f, l = 0.f;
    float oa[DD];
#pragma unroll
    for (int d = 0; d < DD; d++) oa[d] = 0.f;

    __shared__ float ks[16][DD];
    __shared__ float vs[16][DD];

    for (int t = 0; t < 25; t++) {
        const bool is_glob = (t == 24);
        const int p0 = is_glob ? 0 : (n * CW - CW + t * 16);
        __syncthreads();
        for (int f = threadIdx.x; f < 256; f += 128) {
            int j  = f >> 4;
            int d4 = (f & 15) * 4;
            int p  = p0 + j;
            int pc = min(max(p, 0), SS - 1);
            long base = (long)(b * SS + pc) * HH + h * DD + d4;
            *(float4*)&ks[j][d4] = *(const float4*)&k[base];
            *(float4*)&vs[j][d4] = *(const float4*)&v[base];
        }
        __syncthreads();

        float sc[16];
        float tmax = -1e30f;
#pragma unroll
        for (int j = 0; j < 16; j++) {
            int p = p0 + j;
            bool valid = is_glob || ((abs(p - s_q) <= CW) && (p >= GT) && (p < SS));
            float s = -1e30f;
            if (valid) {
                s = 0.f;
#pragma unroll
                for (int d4 = 0; d4 < DD; d4 += 4) {
                    float4 kk = *(const float4*)&ks[j][d4];
                    s += qr[d4] * kk.x + qr[d4 + 1] * kk.y + qr[d4 + 2] * kk.z + qr[d4 + 3] * kk.w;
                }
            }
            sc[j] = s;
            tmax = fmaxf(tmax, s);
        }
        if (tmax > -1e29f) {
            float mnew = fmaxf(m, tmax);
            float alpha = __expf(m - mnew);
            l *= alpha;
#pragma unroll
            for (int d = 0; d < DD; d++) oa[d] *= alpha;
#pragma unroll
            for (int j = 0; j < 16; j++) {
                if (sc[j] > -1e29f) {
                    float pj = __expf(sc[j] - mnew);
                    l += pj;
#pragma unroll
                    for (int d4 = 0; d4 < DD; d4 += 4) {
                        float4 vv = *(const float4*)&vs[j][d4];
                        oa[d4]     += pj * vv.x;
                        oa[d4 + 1] += pj * vv.y;
                        oa[d4 + 2] += pj * vv.z;
                        oa[d4 + 3] += pj * vv.w;
                    }
                }
            }
            m = mnew;
        }
    }
    float inv = 1.f / l;
    float* orow = o + ((long)(b * SS + s_q) * HH + h * DD);
#pragma unroll
    for (int d = 0; d < DD; d++) orow[d] = oa[d] * inv;
}

// ---------------- global-query attention: block per (g,h,b) ----------------
__global__ void __launch_bounds__(128)
glob_attn_kernel(const float* __restrict__ q, const float* __restrict__ k,
                 const float* __restrict__ v, float* __restrict__ o)
{
    const int g = blockIdx.x, h = blockIdx.y, b = blockIdx.z;
    const int tid = threadIdx.x;

    __shared__ float qs[DD];
    __shared__ float sc[SS];
    __shared__ float red[4];
    __shared__ float part[2][DD];

    if (tid < DD) qs[tid] = q[(long)(b * SS + g) * HH + h * DD + tid];
    __syncthreads();

    // pass 1: scores + max
    float lm = -1e30f;
    for (int s = tid; s < SS; s += 128) {
        const float* kr = k + ((long)(b * SS + s) * HH + h * DD);
        float acc = 0.f;
#pragma unroll
        for (int d4 = 0; d4 < DD; d4 += 4) {
            float4 kk = *(const float4*)&kr[d4];
            acc += qs[d4] * kk.x + qs[d4 + 1] * kk.y + qs[d4 + 2] * kk.z + qs[d4 + 3] * kk.w;
        }
        sc[s] = acc;
        lm = fmaxf(lm, acc);
    }
#pragma unroll
    for (int off = 16; off > 0; off >>= 1)
        lm = fmaxf(lm, __shfl_xor_sync(0xffffffffu, lm, off));
    if ((tid & 31) == 0) red[tid >> 5] = lm;
    __syncthreads();
    float m = fmaxf(fmaxf(red[0], red[1]), fmaxf(red[2], red[3]));

    // pass 2: exp + sum
    float ls = 0.f;
    for (int s = tid; s < SS; s += 128) {
        float e = __expf(sc[s] - m);
        sc[s] = e;
        ls += e;
    }
#pragma unroll
    for (int off = 16; off > 0; off >>= 1)
        ls += __shfl_xor_sync(0xffffffffu, ls, off);
    __syncthreads();
    if ((tid & 31) == 0) red[tid >> 5] = ls;
    __syncthreads();
    float l = red[0] + red[1] + red[2] + red[3];

    // pass 3: output
    const int d = tid & 63;
    const int half = tid >> 6;
    float acc = 0.f;
    const int s0 = half * (SS / 2);
#pragma unroll 4
    for (int s = s0; s < s0 + SS / 2; s++)
        acc += sc[s] * v[(long)(b * SS + s) * HH + h * DD + d];
    part[half][d] = acc;
    __syncthreads();
    if (tid < DD) {
        float inv = 1.f / l;
        o[(long)(b * SS + g) * HH + h * DD + tid] = (part[0][tid] + part[1][tid]) * inv;
    }
}

// ---------------- pair gather + classifier head ----------------
__global__ void __launch_bounds__(128)
head_kernel(const float* __restrict__ x, const int* __restrict__ pairs,
            const float* __restrict__ Wh, const float* __restrict__ bh,
            float* __restrict__ out)
{
    const int bp = blockIdx.x;
    const int b = bp >> 7;
    const int i = pairs[bp * 2 + 0];
    const int j = pairs[bp * 2 + 1];
    const float* xi = x + (long)(b * SS + i) * HH;
    const float* xj = x + (long)(b * SS + j) * HH;

    float acc[NLC] = {0.f, 0.f, 0.f};
    for (int d = threadIdx.x; d < 2 * HH; d += 128) {
        float e = (d < HH) ? xi[d] : xj[d - HH];
        acc[0] += e * Wh[d * NLC + 0];
        acc[1] += e * Wh[d * NLC + 1];
        acc[2] += e * Wh[d * NLC + 2];
    }
#pragma unroll
    for (int o = 16; o > 0; o >>= 1) {
#pragma unroll
        for (int c = 0; c < NLC; c++)
            acc[c] += __shfl_xor_sync(0xffffffffu, acc[c], o);
    }
    __shared__ float sm[NLC][4];
    int w = threadIdx.x >> 5;
    if ((threadIdx.x & 31) == 0) {
#pragma unroll
        for (int c = 0; c < NLC; c++) sm[c][w] = acc[c];
    }
    __syncthreads();
    if (threadIdx.x < NLC) {
        float s = sm[threadIdx.x][0] + sm[threadIdx.x][1] + sm[threadIdx.x][2] + sm[threadIdx.x][3];
        out[bp * NLC + threadIdx.x] = s + bh[threadIdx.x];
    }
}

// ---------------- host orchestration ----------------
extern "C" void kernel_launch(void* const* d_in, const int* in_sizes, int n_in,
                              void* d_out, int out_size)
{
    const int*   input_ids    = (const int*)  d_in[0];
    const int*   pair_indices = (const int*)  d_in[1];
    const float* emb          = (const float*)d_in[2];
    const float* Wq  = (const float*)d_in[3];
    const float* bq  = (const float*)d_in[4];
    const float* Wk  = (const float*)d_in[5];
    const float* bk  = (const float*)d_in[6];
    const float* Wv  = (const float*)d_in[7];
    const float* bv  = (const float*)d_in[8];
    const float* Wo  = (const float*)d_in[9];
    const float* bo  = (const float*)d_in[10];
    const float* ln1g = (const float*)d_in[11];
    const float* ln1b = (const float*)d_in[12];
    const float* Wf1 = (const float*)d_in[13];
    const float* bf1 = (const float*)d_in[14];
    const float* Wf2 = (const float*)d_in[15];
    const float* bf2 = (const float*)d_in[16];
    const float* ln2g = (const float*)d_in[17];
    const float* ln2b = (const float*)d_in[18];
    const float* Wh  = (const float*)d_in[19];
    const float* bh  = (const float*)d_in[20];
    float* out = (float*)d_out;

    float *x, *qb, *kb, *vb, *ob, *tb, *hb;
    cudaGetSymbolAddress((void**)&x,  g_x);
    cudaGetSymbolAddress((void**)&qb, g_q);
    cudaGetSymbolAddress((void**)&kb, g_k);
    cudaGetSymbolAddress((void**)&vb, g_v);
    cudaGetSymbolAddress((void**)&ob, g_o);
    cudaGetSymbolAddress((void**)&tb, g_t);
    cudaGetSymbolAddress((void**)&hb, g_h);

    {
        int total = MROWS * HH;
        embed_kernel<<<(total + 255) / 256, 256>>>(input_ids, emb, x);
    }

    const dim3 gemmHH((HH / GN), (MROWS / GM));   // 12 x 32
    const dim3 gemmFF((FF / GN), (MROWS / GM));   // 48 x 32
    const dim3 attnGrid(SS / CW, NHH, BB);
    const dim3 globGrid(GT, NHH, BB);

    for (int l = 0; l < LL; l++) {
        const float* wq = Wq  + (long)l * HH * HH;
        const float* wk = Wk  + (long)l * HH * HH;
        const float* wv = Wv  + (long)l * HH * HH;
        const float* wo = Wo  + (long)l * HH * HH;
        const float* w1 = Wf1 + (long)l * HH * FF;
        const float* w2 = Wf2 + (long)l * FF * HH;

        gemm_kernel<<<gemmHH, 128>>>(x, wq, bq + l * HH, nullptr, qb, MROWS, HH, HH, 0.125f, 0);
        gemm_kernel<<<gemmHH, 128>>>(x, wk, bk + l * HH, nullptr, kb, MROWS, HH, HH, 1.0f,   0);
        gemm_kernel<<<gemmHH, 128>>>(x, wv, bv + l * HH, nullptr, vb, MROWS, HH, HH, 1.0f,   0);

        band_attn_kernel<<<attnGrid, 128>>>(qb, kb, vb, ob);
        glob_attn_kernel<<<globGrid, 128>>>(qb, kb, vb, ob);

        gemm_kernel<<<gemmHH, 128>>>(ob, wo, bo + l * HH, x, tb, MROWS, HH, HH, 1.0f, 1);
        ln_kernel<<<MROWS, 256>>>(tb, ln1g + l * HH, ln1b + l * HH, x);

        gemm_kernel<<<gemmFF, 128>>>(x, w1, bf1 + l * FF, nullptr, hb, MROWS, FF, HH, 1.0f, 2);
        gemm_kernel<<<gemmHH, 128>>>(hb, w2, bf2 + l * HH, x, tb, MROWS, HH, FF, 1.0f, 1);
        ln_kernel<<<MROWS, 256>>>(tb, ln2g + l * HH, ln2b + l * HH, x);
    }

    head_kernel<<<BB * PP, 128>>>(x, pair_indices, Wh, bh, out);
}

// round 4
// speedup vs baseline: 3.2199x; 1.8697x over previous
#include <cuda_runtime.h>
#include <cuda_fp16.h>
#include <math.h>
#include <stdint.h>

// ---------------- problem constants ----------------
#define BB 2
#define SS 2048
#define HH 768
#define NHH 12
#define DD 64
#define LL 4
#define CW 128
#define GT 16
#define PP 128
#define NLC 3
#define FF (4*HH)
#define MROWS (BB*SS)

// ---------------- scratch ----------------
__device__ float  g_x [MROWS*HH];
__device__ float  g_q [MROWS*HH];
__device__ float  g_k [MROWS*HH];
__device__ float  g_v [MROWS*HH];
__device__ float  g_t [MROWS*HH];
__device__ __half g_xh[MROWS*HH];
__device__ __half g_o16[MROWS*HH];
__device__ __half g_h16[MROWS*FF];
// fp16 weights: Wq,Wk,Wv,Wo (L*H*H each), Wf1 (L*H*FF), Wf2 (L*FF*H)
#define WQOFF  0
#define WKOFF  (LL*HH*HH)
#define WVOFF  (2*LL*HH*HH)
#define WOOFF  (3*LL*HH*HH)
#define WF1OFF (4*LL*HH*HH)
#define WF2OFF (4*LL*HH*HH + LL*HH*FF)
#define WTOTAL (4*LL*HH*HH + 2*LL*HH*FF)
__device__ __half g_wbuf[WTOTAL];

// ---------------- fp32 -> fp16 bulk convert ----------------
__global__ void f2h_kernel(const float* __restrict__ s, __half* __restrict__ d, int n)
{
    int i = (blockIdx.x * 256 + threadIdx.x) * 8;
    if (i >= n) return;
    float4 v0 = *(const float4*)&s[i];
    float4 v1 = *(const float4*)&s[i + 4];
    __half2 h0 = __floats2half2_rn(v0.x, v0.y);
    __half2 h1 = __floats2half2_rn(v0.z, v0.w);
    __half2 h2 = __floats2half2_rn(v1.x, v1.y);
    __half2 h3 = __floats2half2_rn(v1.z, v1.w);
    uint4 o;
    o.x = *reinterpret_cast<unsigned*>(&h0);
    o.y = *reinterpret_cast<unsigned*>(&h1);
    o.z = *reinterpret_cast<unsigned*>(&h2);
    o.w = *reinterpret_cast<unsigned*>(&h3);
    *(uint4*)&d[i] = o;
}

// ---------------- embedding gather (fp32 + fp16 outputs) ----------------
__global__ void embed_kernel(const int* __restrict__ ids,
                             const float* __restrict__ emb,
                             float* __restrict__ x, __half* __restrict__ xh)
{
    int idx = blockIdx.x * blockDim.x + threadIdx.x;
    if (idx >= MROWS * HH) return;
    int tok = idx / HH;
    int d   = idx - tok * HH;
    float e = emb[(long)ids[tok] * HH + d];
    x[idx]  = e;
    xh[idx] = __float2half(e);
}

// ---------------- fp16 tensor-core GEMM ----------------
// C[M,N] = epilogue(A[M,K](fp16) @ W[K,N](fp16) + bias)
// CTA 128x64, 4 warps (warp 32x64), k-stage 16, double-buffered.
// mode 0: Cf = scale*(AW+b); mode 1: Cf = AW+b+R; mode 2: Ch = gelu(AW+b)
#define GM 128
#define GN 64
#define APITCH 12

__device__ __forceinline__ void mma_f16(float* d, const unsigned* a, const unsigned* b) {
    asm volatile(
        "mma.sync.aligned.m16n8k16.row.col.f32.f16.f16.f32 "
        "{%0,%1,%2,%3}, {%4,%5,%6,%7}, {%8,%9}, {%0,%1,%2,%3};\n"
        : "+f"(d[0]), "+f"(d[1]), "+f"(d[2]), "+f"(d[3])
        : "r"(a[0]), "r"(a[1]), "r"(a[2]), "r"(a[3]),
          "r"(b[0]), "r"(b[1]));
}

__global__ void __launch_bounds__(128)
gemm16_kernel(const __half* __restrict__ A, const __half* __restrict__ W,
              const float* __restrict__ bias, const float* __restrict__ R,
              float* __restrict__ Cf, __half* __restrict__ Ch,
              int M, int N, int K, float scale, int mode)
{
    // A: packed half2 along k, [m][pitch12] uint32; 8 words used per k16 stage
    __shared__ unsigned As[2][GM][APITCH];
    // B: [k][n] fp16, 128B rows, SW128 swizzled (chunk ^= k&7)
    __shared__ __half  Bs[2][16][GN];

    const int tid  = threadIdx.x;
    const int w    = tid >> 5;
    const int lane = tid & 31;
    const int gid  = lane >> 2;
    const int tig  = lane & 3;
    const int row0 = blockIdx.y * GM;
    const int col0 = blockIdx.x * GN;

    // B staging: thread -> one 16B chunk: k=tid>>3, n0=(tid&7)*8
    const int bk = tid >> 3;
    const int bn = (tid & 7) * 8;
    const int bs_byte = bk * 128 + ((((bn >> 3) ^ (bk & 7))) << 4);
    char* bsraw = (char*)&Bs[0][0][0];

    // ldmatrix lane addressing
    const int lsel = lane >> 3;            // 0..3
    const int lk   = (lsel & 1) * 8 + (lane & 7);   // row k 0..15
    const int lnc  = (lsel >> 1);          // n8-subtile within pair
    unsigned bs_smem = (unsigned)__cvta_generic_to_shared(&Bs[0][0][0]);

    float acc[2][8][4];
#pragma unroll
    for (int mt = 0; mt < 2; mt++)
#pragma unroll
        for (int nt = 0; nt < 8; nt++)
#pragma unroll
            for (int u = 0; u < 4; u++) acc[mt][nt][u] = 0.f;

    const int nk = K / 16;

    // ---- prologue: stage 0 ----
    {
        const __half* arow = &A[(long)(row0 + tid) * K];
        uint4 a0 = *(const uint4*)&arow[0];
        uint4 a1 = *(const uint4*)&arow[8];
        *(uint4*)&As[0][tid][0] = a0;
        *(uint4*)&As[0][tid][4] = a1;
        uint4 bv = *(const uint4*)&W[(long)bk * N + col0 + bn];
        *(uint4*)(bsraw + bs_byte) = bv;
    }
    __syncthreads();

    for (int kt = 0; kt < nk; kt++) {
        const int buf = kt & 1;
        const bool more = (kt + 1 < nk);
        uint4 ra0, ra1, rbv;
        if (more) {
            int k0 = (kt + 1) * 16;
            const __half* arow = &A[(long)(row0 + tid) * K + k0];
            ra0 = *(const uint4*)&arow[0];
            ra1 = *(const uint4*)&arow[8];
            rbv = *(const uint4*)&W[(long)(k0 + bk) * N + col0 + bn];
        }

        // ---- fragments ----
        unsigned afr[2][4];
#pragma unroll
        for (int mt = 0; mt < 2; mt++) {
            int m = w * 32 + mt * 16 + gid;
            afr[mt][0] = As[buf][m    ][tig];
            afr[mt][1] = As[buf][m + 8][tig];
            afr[mt][2] = As[buf][m    ][tig + 4];
            afr[mt][3] = As[buf][m + 8][tig + 4];
        }
        unsigned bfr[8][2];
#pragma unroll
        for (int ntp = 0; ntp < 4; ntp++) {
            int chunk = (ntp * 2 + lnc) ^ (lk & 7);
            unsigned addr = bs_smem + buf * 2048 + lk * 128 + chunk * 16;
            unsigned r0, r1, r2, r3;
            asm volatile(
                "ldmatrix.sync.aligned.m8n8.x4.trans.shared.b16 {%0,%1,%2,%3}, [%4];"
                : "=r"(r0), "=r"(r1), "=r"(r2), "=r"(r3) : "r"(addr));
            bfr[ntp * 2    ][0] = r0;
            bfr[ntp * 2    ][1] = r1;
            bfr[ntp * 2 + 1][0] = r2;
            bfr[ntp * 2 + 1][1] = r3;
        }
#pragma unroll
        for (int mt = 0; mt < 2; mt++)
#pragma unroll
            for (int nt = 0; nt < 8; nt++)
                mma_f16(acc[mt][nt], afr[mt], bfr[nt]);

        if (more) {
            const int nb = buf ^ 1;
            *(uint4*)&As[nb][tid][0] = ra0;
            *(uint4*)&As[nb][tid][4] = ra1;
            *(uint4*)(bsraw + nb * 2048 + bs_byte) = rbv;
            __syncthreads();
        }
    }

    // ---- epilogue ----
#pragma unroll
    for (int nt = 0; nt < 8; nt++) {
        const int cc = col0 + nt * 8 + 2 * tig;
        float2 bv = *(const float2*)&bias[cc];
#pragma unroll
        for (int mt = 0; mt < 2; mt++) {
            int r0 = row0 + w * 32 + mt * 16 + gid;
#pragma unroll
            for (int half_ = 0; half_ < 2; half_++) {
                int rr = r0 + half_ * 8;
                float vx = acc[mt][nt][half_ * 2 + 0] + bv.x;
                float vy = acc[mt][nt][half_ * 2 + 1] + bv.y;
                if (mode == 0) {
                    vx *= scale; vy *= scale;
                    *(float2*)&Cf[(long)rr * N + cc] = make_float2(vx, vy);
                } else if (mode == 1) {
                    float2 rrv = *(const float2*)&R[(long)rr * N + cc];
                    vx += rrv.x; vy += rrv.y;
                    *(float2*)&Cf[(long)rr * N + cc] = make_float2(vx, vy);
                } else {
                    float t0 = vx, t1 = vy;
                    vx = 0.5f * t0 * (1.f + tanhf(0.7978845608028654f * (t0 + 0.044715f * t0 * t0 * t0)));
                    vy = 0.5f * t1 * (1.f + tanhf(0.7978845608028654f * (t1 + 0.044715f * t1 * t1 * t1)));
                    *(__half2*)&Ch[(long)rr * N + cc] = __floats2half2_rn(vx, vy);
                }
            }
        }
    }
}

// ---------------- layernorm over H=768 (fp32 + fp16 outputs) ----------------
__global__ void __launch_bounds__(256)
ln_kernel(const float* __restrict__ in, const float* __restrict__ g,
          const float* __restrict__ b, float* __restrict__ out, __half* __restrict__ outh)
{
    const int row = blockIdx.x;
    const float* x = in + (long)row * HH;
    float v0[3];
    float s = 0.f, s2 = 0.f;
#pragma unroll
    for (int i = 0; i < 3; i++) {
        float t = x[threadIdx.x + i * 256];
        v0[i] = t; s += t; s2 += t * t;
    }
#pragma unroll
    for (int o = 16; o > 0; o >>= 1) {
        s  += __shfl_xor_sync(0xffffffffu, s, o);
        s2 += __shfl_xor_sync(0xffffffffu, s2, o);
    }
    __shared__ float red0[8], red1[8];
    int w = threadIdx.x >> 5;
    if ((threadIdx.x & 31) == 0) { red0[w] = s; red1[w] = s2; }
    __syncthreads();
    if (threadIdx.x < 32) {
        s  = (threadIdx.x < 8) ? red0[threadIdx.x] : 0.f;
        s2 = (threadIdx.x < 8) ? red1[threadIdx.x] : 0.f;
#pragma unroll
        for (int o = 4; o > 0; o >>= 1) {
            s  += __shfl_xor_sync(0xffffffffu, s, o);
            s2 += __shfl_xor_sync(0xffffffffu, s2, o);
        }
        if (threadIdx.x == 0) { red0[0] = s; red1[0] = s2; }
    }
    __syncthreads();
    float mean = red0[0] * (1.f / HH);
    float var  = red1[0] * (1.f / HH) - mean * mean;
    float rstd = rsqrtf(var + 1e-5f);
#pragma unroll
    for (int i = 0; i < 3; i++) {
        int c = threadIdx.x + i * 256;
        float val = (v0[i] - mean) * rstd * g[c] + b[c];
        out [(long)row * HH + c] = val;
        outh[(long)row * HH + c] = __float2half(val);
    }
}

// ---------------- banded attention (fp16 output) ----------------
__global__ void __launch_bounds__(128)
band_attn_kernel(const float* __restrict__ q, const float* __restrict__ k,
                 const float* __restrict__ v, __half* __restrict__ o)
{
    const int n = blockIdx.x, h = blockIdx.y, b = blockIdx.z;
    const int qi = threadIdx.x;
    const int s_q = n * CW + qi;

    const float* qrow = q + ((long)(b * SS + s_q) * HH + h * DD);
    float qr[DD];
#pragma unroll
    for (int d = 0; d < DD; d++) qr[d] = qrow[d];

    float m = -1e30f, l = 0.f;
    float oa[DD];
#pragma unroll
    for (int d = 0; d < DD; d++) oa[d] = 0.f;

    __shared__ float ks[16][DD];
    __shared__ float vs[16][DD];

    for (int t = 0; t < 25; t++) {
        const bool is_glob = (t == 24);
        const int p0 = is_glob ? 0 : (n * CW - CW + t * 16);
        __syncthreads();
        for (int f = threadIdx.x; f < 256; f += 128) {
            int j  = f >> 4;
            int d4 = (f & 15) * 4;
            int p  = p0 + j;
            int pc = min(max(p, 0), SS - 1);
            long base = (long)(b * SS + pc) * HH + h * DD + d4;
            *(float4*)&ks[j][d4] = *(const float4*)&k[base];
            *(float4*)&vs[j][d4] = *(const float4*)&v[base];
        }
        __syncthreads();

        float sc[16];
        float tmax = -1e30f;
#pragma unroll
        for (int j = 0; j < 16; j++) {
            int p = p0 + j;
            bool valid = is_glob || ((abs(p - s_q) <= CW) && (p >= GT) && (p < SS));
            float s = -1e30f;
            if (valid) {
                s = 0.f;
#pragma unroll
                for (int d4 = 0; d4 < DD; d4 += 4) {
                    float4 kk = *(const float4*)&ks[j][d4];
                    s += qr[d4] * kk.x + qr[d4 + 1] * kk.y + qr[d4 + 2] * kk.z + qr[d4 + 3] * kk.w;
                }
            }
            sc[j] = s;
            tmax = fmaxf(tmax, s);
        }
        if (tmax > -1e29f) {
            float mnew = fmaxf(m, tmax);
            float alpha = __expf(m - mnew);
            l *= alpha;
#pragma unroll
            for (int d = 0; d < DD; d++) oa[d] *= alpha;
#pragma unroll
            for (int j = 0; j < 16; j++) {
                if (sc[j] > -1e29f) {
                    float pj = __expf(sc[j] - mnew);
                    l += pj;
#pragma unroll
                    for (int d4 = 0; d4 < DD; d4 += 4) {
                        float4 vv = *(const float4*)&vs[j][d4];
                        oa[d4]     += pj * vv.x;
                        oa[d4 + 1] += pj * vv.y;
                        oa[d4 + 2] += pj * vv.z;
                        oa[d4 + 3] += pj * vv.w;
                    }
                }
            }
            m = mnew;
        }
    }
    float inv = 1.f / l;
    __half* orow = o + ((long)(b * SS + s_q) * HH + h * DD);
#pragma unroll
    for (int d = 0; d < DD; d += 2)
        *(__half2*)&orow[d] = __floats2half2_rn(oa[d] * inv, oa[d + 1] * inv);
}

// ---------------- global-query attention: block per (g,h,b) ----------------
__global__ void __launch_bounds__(128)
glob_attn_kernel(const float* __restrict__ q, const float* __restrict__ k,
                 const float* __restrict__ v, __half* __restrict__ o)
{
    const int g = blockIdx.x, h = blockIdx.y, b = blockIdx.z;
    const int tid = threadIdx.x;

    __shared__ float qs[DD];
    __shared__ float sc[SS];
    __shared__ float red[4];
    __shared__ float part[2][DD];

    if (tid < DD) qs[tid] = q[(long)(b * SS + g) * HH + h * DD + tid];
    __syncthreads();

    float lm = -1e30f;
    for (int s = tid; s < SS; s += 128) {
        const float* kr = k + ((long)(b * SS + s) * HH + h * DD);
        float acc = 0.f;
#pragma unroll
        for (int d4 = 0; d4 < DD; d4 += 4) {
            float4 kk = *(const float4*)&kr[d4];
            acc += qs[d4] * kk.x + qs[d4 + 1] * kk.y + qs[d4 + 2] * kk.z + qs[d4 + 3] * kk.w;
        }
        sc[s] = acc;
        lm = fmaxf(lm, acc);
    }
#pragma unroll
    for (int off = 16; off > 0; off >>= 1)
        lm = fmaxf(lm, __shfl_xor_sync(0xffffffffu, lm, off));
    if ((tid & 31) == 0) red[tid >> 5] = lm;
    __syncthreads();
    float m = fmaxf(fmaxf(red[0], red[1]), fmaxf(red[2], red[3]));

    float ls = 0.f;
    for (int s = tid; s < SS; s += 128) {
        float e = __expf(sc[s] - m);
        sc[s] = e;
        ls += e;
    }
#pragma unroll
    for (int off = 16; off > 0; off >>= 1)
        ls += __shfl_xor_sync(0xffffffffu, ls, off);
    __syncthreads();
    if ((tid & 31) == 0) red[tid >> 5] = ls;
    __syncthreads();
    float l = red[0] + red[1] + red[2] + red[3];

    const int d = tid & 63;
    const int half_ = tid >> 6;
    float acc = 0.f;
    const int s0 = half_ * (SS / 2);
#pragma unroll 4
    for (int s = s0; s < s0 + SS / 2; s++)
        acc += sc[s] * v[(long)(b * SS + s) * HH + h * DD + d];
    part[half_][d] = acc;
    __syncthreads();
    if (tid < DD) {
        float inv = 1.f / l;
        o[(long)(b * SS + g) * HH + h * DD + tid] = __float2half((part[0][tid] + part[1][tid]) * inv);
    }
}

// ---------------- pair gather + classifier head ----------------
__global__ void __launch_bounds__(128)
head_kernel(const float* __restrict__ x, const int* __restrict__ pairs,
            const float* __restrict__ Wh, const float* __restrict__ bh,
            float* __restrict__ out)
{
    const int bp = blockIdx.x;
    const int b = bp >> 7;
    const int i = pairs[bp * 2 + 0];
    const int j = pairs[bp * 2 + 1];
    const float* xi = x + (long)(b * SS + i) * HH;
    const float* xj = x + (long)(b * SS + j) * HH;

    float acc[NLC] = {0.f, 0.f, 0.f};
    for (int d = threadIdx.x; d < 2 * HH; d += 128) {
        float e = (d < HH) ? xi[d] : xj[d - HH];
        acc[0] += e * Wh[d * NLC + 0];
        acc[1] += e * Wh[d * NLC + 1];
        acc[2] += e * Wh[d * NLC + 2];
    }
#pragma unroll
    for (int o = 16; o > 0; o >>= 1) {
#pragma unroll
        for (int c = 0; c < NLC; c++)
            acc[c] += __shfl_xor_sync(0xffffffffu, acc[c], o);
    }
    __shared__ float sm[NLC][4];
    int w = threadIdx.x >> 5;
    if ((threadIdx.x & 31) == 0) {
#pragma unroll
        for (int c = 0; c < NLC; c++) sm[c][w] = acc[c];
    }
    __syncthreads();
    if (threadIdx.x < NLC) {
        float s = sm[threadIdx.x][0] + sm[threadIdx.x][1] + sm[threadIdx.x][2] + sm[threadIdx.x][3];
        out[bp * NLC + threadIdx.x] = s + bh[threadIdx.x];
    }
}

// ---------------- host orchestration ----------------
extern "C" void kernel_launch(void* const* d_in, const int* in_sizes, int n_in,
                              void* d_out, int out_size)
{
    const int*   input_ids    = (const int*)  d_in[0];
    const int*   pair_indices = (const int*)  d_in[1];
    const float* emb          = (const float*)d_in[2];
    const float* Wq  = (const float*)d_in[3];
    const float* bq  = (const float*)d_in[4];
    const float* Wk  = (const float*)d_in[5];
    const float* bk  = (const float*)d_in[6];
    const float* Wv  = (const float*)d_in[7];
    const float* bv  = (const float*)d_in[8];
    const float* Wo  = (const float*)d_in[9];
    const float* bo  = (const float*)d_in[10];
    const float* ln1g = (const float*)d_in[11];
    const float* ln1b = (const float*)d_in[12];
    const float* Wf1 = (const float*)d_in[13];
    const float* bf1 = (const float*)d_in[14];
    const float* Wf2 = (const float*)d_in[15];
    const float* bf2 = (const float*)d_in[16];
    const float* ln2g = (const float*)d_in[17];
    const float* ln2b = (const float*)d_in[18];
    const float* Wh  = (const float*)d_in[19];
    const float* bh  = (const float*)d_in[20];
    float* out = (float*)d_out;

    float *x, *qb, *kb, *vb, *tb;
    __half *xh, *o16, *h16, *wbuf;
    cudaGetSymbolAddress((void**)&x,  g_x);
    cudaGetSymbolAddress((void**)&qb, g_q);
    cudaGetSymbolAddress((void**)&kb, g_k);
    cudaGetSymbolAddress((void**)&vb, g_v);
    cudaGetSymbolAddress((void**)&tb, g_t);
    cudaGetSymbolAddress((void**)&xh,  g_xh);
    cudaGetSymbolAddress((void**)&o16, g_o16);
    cudaGetSymbolAddress((void**)&h16, g_h16);
    cudaGetSymbolAddress((void**)&wbuf, g_wbuf);

    // weight conversion fp32 -> fp16 (once per call)
    {
        int nHH = LL * HH * HH;       // 2359296
        int nFF = LL * HH * FF;       // 9437184
        int gHH = (nHH / 8 + 255) / 256;
        int gFF = (nFF / 8 + 255) / 256;
        f2h_kernel<<<gHH, 256>>>(Wq,  wbuf + WQOFF,  nHH);
        f2h_kernel<<<gHH, 256>>>(Wk,  wbuf + WKOFF,  nHH);
        f2h_kernel<<<gHH, 256>>>(Wv,  wbuf + WVOFF,  nHH);
        f2h_kernel<<<gHH, 256>>>(Wo,  wbuf + WOOFF,  nHH);
        f2h_kernel<<<gFF, 256>>>(Wf1, wbuf + WF1OFF, nFF);
        f2h_kernel<<<gFF, 256>>>(Wf2, wbuf + WF2OFF, nFF);
    }

    {
        int total = MROWS * HH;
        embed_kernel<<<(total + 255) / 256, 256>>>(input_ids, emb, x, xh);
    }

    const dim3 gemmHH((HH / GN), (MROWS / GM));   // 12 x 32
    const dim3 gemmFF((FF / GN), (MROWS / GM));   // 48 x 32
    const dim3 attnGrid(SS / CW, NHH, BB);
    const dim3 globGrid(GT, NHH, BB);

    for (int l = 0; l < LL; l++) {
        const __half* wq = wbuf + WQOFF  + (long)l * HH * HH;
        const __half* wk = wbuf + WKOFF  + (long)l * HH * HH;
        const __half* wv = wbuf + WVOFF  + (long)l * HH * HH;
        const __half* wo = wbuf + WOOFF  + (long)l * HH * HH;
        const __half* w1 = wbuf + WF1OFF + (long)l * HH * FF;
        const __half* w2 = wbuf + WF2OFF + (long)l * FF * HH;

        gemm16_kernel<<<gemmHH, 128>>>(xh, wq, bq + l * HH, nullptr, qb, nullptr, MROWS, HH, HH, 0.125f, 0);
        gemm16_kernel<<<gemmHH, 128>>>(xh, wk, bk + l * HH, nullptr, kb, nullptr, MROWS, HH, HH, 1.0f,   0);
        gemm16_kernel<<<gemmHH, 128>>>(xh, wv, bv + l * HH, nullptr, vb, nullptr, MROWS, HH, HH, 1.0f,   0);

        band_attn_kernel<<<attnGrid, 128>>>(qb, kb, vb, o16);
        glob_attn_kernel<<<globGrid, 128>>>(qb, kb, vb, o16);

        gemm16_kernel<<<gemmHH, 128>>>(o16, wo, bo + l * HH, x, tb, nullptr, MROWS, HH, HH, 1.0f, 1);
        ln_kernel<<<MROWS, 256>>>(tb, ln1g + l * HH, ln1b + l * HH, x, xh);

        gemm16_kernel<<<gemmFF, 128>>>(xh, w1, bf1 + l * FF, nullptr, nullptr, h16, MROWS, FF, HH, 1.0f, 2);
        gemm16_kernel<<<gemmHH, 128>>>(h16, w2, bf2 + l * HH, x, tb, nullptr, MROWS, HH, FF, 1.0f, 1);
        ln_kernel<<<MROWS, 256>>>(tb, ln2g + l * HH, ln2b + l * HH, x, xh);
    }

    head_kernel<<<BB * PP, 128>>>(x, pair_indices, Wh, bh, out);
}

// round 5
// speedup vs baseline: 3.5029x; 1.0879x over previous
#include <cuda_runtime.h>
#include <cuda_fp16.h>
#include <math.h>
#include <stdint.h>

// ---------------- problem constants ----------------
#define BB 2
#define SS 2048
#define HH 768
#define NHH 12
#define DD 64
#define LL 4
#define CW 128
#define GT 16
#define PP 128
#define NLC 3
#define FF (4*HH)
#define MROWS (BB*SS)
#define QKVW (3*HH)   // 2304

// ---------------- scratch ----------------
__device__ float  g_x   [MROWS*HH];
__device__ float  g_qkv [MROWS*QKVW];
__device__ float  g_t   [MROWS*HH];
__device__ __half g_xh  [MROWS*HH];
__device__ __half g_o16 [MROWS*HH];
__device__ __half g_h16 [MROWS*FF];
__device__ float  g_bqkv[LL*QKVW];
// fp16 weights: packed QKV (L*H*2304), Wo (L*H*H), Wf1 (L*H*FF), Wf2 (L*FF*H)
#define WQKVOFF 0
#define WOOFF   (3*LL*HH*HH)
#define WF1OFF  (4*LL*HH*HH)
#define WF2OFF  (4*LL*HH*HH + LL*HH*FF)
#define WTOTAL  (4*LL*HH*HH + 2*LL*HH*FF)
__device__ __half g_wbuf[WTOTAL];

// ---------------- fp32 -> fp16 bulk convert ----------------
__global__ void f2h_kernel(const float* __restrict__ s, __half* __restrict__ d, int n)
{
    int i = (blockIdx.x * 256 + threadIdx.x) * 8;
    if (i >= n) return;
    float4 v0 = *(const float4*)&s[i];
    float4 v1 = *(const float4*)&s[i + 4];
    __half2 h0 = __floats2half2_rn(v0.x, v0.y);
    __half2 h1 = __floats2half2_rn(v0.z, v0.w);
    __half2 h2 = __floats2half2_rn(v1.x, v1.y);
    __half2 h3 = __floats2half2_rn(v1.z, v1.w);
    uint4 o;
    o.x = *reinterpret_cast<unsigned*>(&h0);
    o.y = *reinterpret_cast<unsigned*>(&h1);
    o.z = *reinterpret_cast<unsigned*>(&h2);
    o.w = *reinterpret_cast<unsigned*>(&h3);
    *(uint4*)&d[i] = o;
}

// ---------------- pack Wq|Wk|Wv -> [L][H][2304] fp16, scale q by 0.125 ----------------
__global__ void pack_qkv_kernel(const float* __restrict__ Wq, const float* __restrict__ Wk,
                                const float* __restrict__ Wv, __half* __restrict__ dst)
{
    long i = ((long)blockIdx.x * 256 + threadIdx.x) * 8;
    if (i >= (long)LL * HH * QKVW) return;
    int l   = (int)(i / (HH * QKVW));
    int rem = (int)(i - (long)l * HH * QKVW);
    int k   = rem / QKVW;
    int j   = rem - k * QKVW;
    int seg = j / HH;
    int jj  = j - seg * HH;
    const float* src = (seg == 0 ? Wq : seg == 1 ? Wk : Wv) + ((long)l * HH + k) * HH + jj;
    float sc = (seg == 0) ? 0.125f : 1.0f;
    float4 v0 = *(const float4*)&src[0];
    float4 v1 = *(const float4*)&src[4];
    __half2 h0 = __floats2half2_rn(v0.x * sc, v0.y * sc);
    __half2 h1 = __floats2half2_rn(v0.z * sc, v0.w * sc);
    __half2 h2 = __floats2half2_rn(v1.x * sc, v1.y * sc);
    __half2 h3 = __floats2half2_rn(v1.z * sc, v1.w * sc);
    uint4 o;
    o.x = *reinterpret_cast<unsigned*>(&h0);
    o.y = *reinterpret_cast<unsigned*>(&h1);
    o.z = *reinterpret_cast<unsigned*>(&h2);
    o.w = *reinterpret_cast<unsigned*>(&h3);
    *(uint4*)&dst[i] = o;
}

__global__ void pack_bqkv_kernel(const float* __restrict__ bq, const float* __restrict__ bk,
                                 const float* __restrict__ bv, float* __restrict__ dst)
{
    int i = blockIdx.x * 256 + threadIdx.x;
    if (i >= LL * QKVW) return;
    int l = i / QKVW;
    int j = i - l * QKVW;
    int seg = j / HH;
    int jj  = j - seg * HH;
    float v = (seg == 0 ? bq[l * HH + jj] * 0.125f : seg == 1 ? bk[l * HH + jj] : bv[l * HH + jj]);
    dst[i] = v;
}

// ---------------- embedding gather ----------------
__global__ void embed_kernel(const int* __restrict__ ids,
                             const float* __restrict__ emb,
                             float* __restrict__ x, __half* __restrict__ xh)
{
    int idx = blockIdx.x * blockDim.x + threadIdx.x;
    if (idx >= MROWS * HH) return;
    int tok = idx / HH;
    int d   = idx - tok * HH;
    float e = emb[(long)ids[tok] * HH + d];
    x[idx]  = e;
    xh[idx] = __float2half(e);
}

// ---------------- fp16 tensor-core GEMM, CTA 128x128, 256 thr, cp.async ----------------
// mode 0: Cf = AW+b; mode 1: Cf = AW+b+R; mode 2: Ch = gelu(AW+b)
#define GM 128
#define GN 128

__device__ __forceinline__ void mma_f16(float* d, const unsigned* a, const unsigned* b) {
    asm volatile(
        "mma.sync.aligned.m16n8k16.row.col.f32.f16.f16.f32 "
        "{%0,%1,%2,%3}, {%4,%5,%6,%7}, {%8,%9}, {%0,%1,%2,%3};\n"
        : "+f"(d[0]), "+f"(d[1]), "+f"(d[2]), "+f"(d[3])
        : "r"(a[0]), "r"(a[1]), "r"(a[2]), "r"(a[3]),
          "r"(b[0]), "r"(b[1]));
}

__device__ __forceinline__ void cp16(unsigned smem, const void* g) {
    asm volatile("cp.async.cg.shared.global [%0], [%1], 16;\n" :: "r"(smem), "l"(g));
}

__global__ void __launch_bounds__(256)
gemm16_kernel(const __half* __restrict__ A, const __half* __restrict__ W,
              const float* __restrict__ bias, const float* __restrict__ R,
              float* __restrict__ Cf, __half* __restrict__ Ch,
              int M, int N, int K, int mode)
{
    // A: [m][pitch12] uint32 (half2 over k); stage = 128*48B = 6KB
    __shared__ unsigned As[2][GM][12];
    // B: [k][n] fp16, 256B rows, 16B chunks XOR-swizzled by (k&7); stage 4KB
    __shared__ __half Bs[2][16][GN];

    const int tid  = threadIdx.x;
    const int w    = tid >> 5;
    const int lane = tid & 31;
    const int gid  = lane >> 2;
    const int tig  = lane & 3;
    const int wm   = (w >> 1) * 32;
    const int wn   = (w & 1) * 64;
    const int row0 = blockIdx.y * GM;
    const int col0 = blockIdx.x * GN;

    // A staging: thread -> row tid>>1, k-chunk (tid&1)
    const int ar = tid >> 1;
    const int ac = tid & 1;
    // B staging: thread -> k row tid>>4, n-chunk tid&15 (swizzled)
    const int bk = tid >> 4;
    const int bc = tid & 15;
    const int bcs = bc ^ (bk & 7);

    const unsigned as_base = (unsigned)__cvta_generic_to_shared(&As[0][0][0]);
    const unsigned bs_base = (unsigned)__cvta_generic_to_shared(&Bs[0][0][0]);
    const unsigned a_dst = as_base + (ar * 12 + ac * 4) * 4;   // byte offset within stage
    const unsigned b_dst = bs_base + bk * 256 + bcs * 16;

    // ldmatrix lane addressing
    const int lsel = lane >> 3;
    const int lk   = (lsel & 1) * 8 + (lane & 7);
    const int lnc  = (lsel >> 1);

    float acc[2][8][4];
#pragma unroll
    for (int mt = 0; mt < 2; mt++)
#pragma unroll
        for (int nt = 0; nt < 8; nt++)
#pragma unroll
            for (int u = 0; u < 4; u++) acc[mt][nt][u] = 0.f;

    const int nk = K / 16;

    // prologue: stage 0
    cp16(a_dst, &A[(long)(row0 + ar) * K + ac * 8]);
    cp16(b_dst, &W[(long)bk * N + col0 + bc * 8]);
    asm volatile("cp.async.commit_group;\n");

    for (int kt = 0; kt < nk; kt++) {
        const int buf = kt & 1;
        asm volatile("cp.async.wait_group 0;\n");
        __syncthreads();

        if (kt + 1 < nk) {
            const int nb = buf ^ 1;
            int k0 = (kt + 1) * 16;
            cp16(a_dst + nb * 6144, &A[(long)(row0 + ar) * K + k0 + ac * 8]);
            cp16(b_dst + nb * 4096, &W[(long)(k0 + bk) * N + col0 + bc * 8]);
            asm volatile("cp.async.commit_group;\n");
        }

        unsigned afr[2][4];
#pragma unroll
        for (int mt = 0; mt < 2; mt++) {
            int m = wm + mt * 16 + gid;
            afr[mt][0] = As[buf][m    ][tig];
            afr[mt][1] = As[buf][m + 8][tig];
            afr[mt][2] = As[buf][m    ][tig + 4];
            afr[mt][3] = As[buf][m + 8][tig + 4];
        }
        unsigned bfr[8][2];
#pragma unroll
        for (int ntp = 0; ntp < 4; ntp++) {
            int ncg = (wn >> 3) + ntp * 2 + lnc;
            int chunk = ncg ^ (lk & 7);
            unsigned addr = bs_base + buf * 4096 + lk * 256 + chunk * 16;
            unsigned r0, r1, r2, r3;
            asm volatile(
                "ldmatrix.sync.aligned.m8n8.x4.trans.shared.b16 {%0,%1,%2,%3}, [%4];"
                : "=r"(r0), "=r"(r1), "=r"(r2), "=r"(r3) : "r"(addr));
            bfr[ntp * 2    ][0] = r0;
            bfr[ntp * 2    ][1] = r1;
            bfr[ntp * 2 + 1][0] = r2;
            bfr[ntp * 2 + 1][1] = r3;
        }
#pragma unroll
        for (int mt = 0; mt < 2; mt++)
#pragma unroll
            for (int nt = 0; nt < 8; nt++)
                mma_f16(acc[mt][nt], afr[mt], bfr[nt]);
    }

    // ---- epilogue ----
#pragma unroll
    for (int nt = 0; nt < 8; nt++) {
        const int cc = col0 + wn + nt * 8 + 2 * tig;
        float2 bv = *(const float2*)&bias[cc];
#pragma unroll
        for (int mt = 0; mt < 2; mt++) {
            int r0 = row0 + wm + mt * 16 + gid;
#pragma unroll
            for (int half_ = 0; half_ < 2; half_++) {
                int rr = r0 + half_ * 8;
                float vx = acc[mt][nt][half_ * 2 + 0] + bv.x;
                float vy = acc[mt][nt][half_ * 2 + 1] + bv.y;
                if (mode == 0) {
                    *(float2*)&Cf[(long)rr * N + cc] = make_float2(vx, vy);
                } else if (mode == 1) {
                    float2 rrv = *(const float2*)&R[(long)rr * N + cc];
                    *(float2*)&Cf[(long)rr * N + cc] = make_float2(vx + rrv.x, vy + rrv.y);
                } else {
                    float t0 = vx, t1 = vy;
                    vx = 0.5f * t0 * (1.f + tanhf(0.7978845608028654f * (t0 + 0.044715f * t0 * t0 * t0)));
                    vy = 0.5f * t1 * (1.f + tanhf(0.7978845608028654f * (t1 + 0.044715f * t1 * t1 * t1)));
                    *(__half2*)&Ch[(long)rr * N + cc] = __floats2half2_rn(vx, vy);
                }
            }
        }
    }
}

// ---------------- layernorm over H=768 ----------------
__global__ void __launch_bounds__(256)
ln_kernel(const float* __restrict__ in, const float* __restrict__ g,
          const float* __restrict__ b, float* __restrict__ out, __half* __restrict__ outh)
{
    const int row = blockIdx.x;
    const float* x = in + (long)row * HH;
    float v0[3];
    float s = 0.f, s2 = 0.f;
#pragma unroll
    for (int i = 0; i < 3; i++) {
        float t = x[threadIdx.x + i * 256];
        v0[i] = t; s += t; s2 += t * t;
    }
#pragma unroll
    for (int o = 16; o > 0; o >>= 1) {
        s  += __shfl_xor_sync(0xffffffffu, s, o);
        s2 += __shfl_xor_sync(0xffffffffu, s2, o);
    }
    __shared__ float red0[8], red1[8];
    int w = threadIdx.x >> 5;
    if ((threadIdx.x & 31) == 0) { red0[w] = s; red1[w] = s2; }
    __syncthreads();
    if (threadIdx.x < 32) {
        s  = (threadIdx.x < 8) ? red0[threadIdx.x] : 0.f;
        s2 = (threadIdx.x < 8) ? red1[threadIdx.x] : 0.f;
#pragma unroll
        for (int o = 4; o > 0; o >>= 1) {
            s  += __shfl_xor_sync(0xffffffffu, s, o);
            s2 += __shfl_xor_sync(0xffffffffu, s2, o);
        }
        if (threadIdx.x == 0) { red0[0] = s; red1[0] = s2; }
    }
    __syncthreads();
    float mean = red0[0] * (1.f / HH);
    float var  = red1[0] * (1.f / HH) - mean * mean;
    float rstd = rsqrtf(var + 1e-5f);
#pragma unroll
    for (int i = 0; i < 3; i++) {
        int c = threadIdx.x + i * 256;
        float val = (v0[i] - mean) * rstd * g[c] + b[c];
        out [(long)row * HH + c] = val;
        outh[(long)row * HH + c] = __float2half(val);
    }
}

// ---------------- banded attention (reads fused qkv, stride QKVW) ----------------
__global__ void __launch_bounds__(128)
band_attn_kernel(const float* __restrict__ qkv, __half* __restrict__ o)
{
    const int n = blockIdx.x, h = blockIdx.y, b = blockIdx.z;
    const int qi = threadIdx.x;
    const int s_q = n * CW + qi;

    const float* qrow = qkv + ((long)(b * SS + s_q) * QKVW + h * DD);
    float qr[DD];
#pragma unroll
    for (int d = 0; d < DD; d++) qr[d] = qrow[d];

    float m = -1e30f, l = 0.f;
    float oa[DD];
#pragma unroll
    for (int d = 0; d < DD; d++) oa[d] = 0.f;

    __shared__ float ks[16][DD];
    __shared__ float vs[16][DD];

    for (int t = 0; t < 25; t++) {
        const bool is_glob = (t == 24);
        const int p0 = is_glob ? 0 : (n * CW - CW + t * 16);
        __syncthreads();
        for (int f = threadIdx.x; f < 256; f += 128) {
            int j  = f >> 4;
            int d4 = (f & 15) * 4;
            int p  = p0 + j;
            int pc = min(max(p, 0), SS - 1);
            long base = (long)(b * SS + pc) * QKVW + h * DD + d4;
            *(float4*)&ks[j][d4] = *(const float4*)&qkv[HH + base];
            *(float4*)&vs[j][d4] = *(const float4*)&qkv[2 * HH + base];
        }
        __syncthreads();

        float sc[16];
        float tmax = -1e30f;
#pragma unroll
        for (int j = 0; j < 16; j++) {
            int p = p0 + j;
            bool valid = is_glob || ((abs(p - s_q) <= CW) && (p >= GT) && (p < SS));
            float s = -1e30f;
            if (valid) {
                s = 0.f;
#pragma unroll
                for (int d4 = 0; d4 < DD; d4 += 4) {
                    float4 kk = *(const float4*)&ks[j][d4];
                    s += qr[d4] * kk.x + qr[d4 + 1] * kk.y + qr[d4 + 2] * kk.z + qr[d4 + 3] * kk.w;
                }
            }
            sc[j] = s;
            tmax = fmaxf(tmax, s);
        }
        if (tmax > -1e29f) {
            float mnew = fmaxf(m, tmax);
            float alpha = __expf(m - mnew);
            l *= alpha;
#pragma unroll
            for (int d = 0; d < DD; d++) oa[d] *= alpha;
#pragma unroll
            for (int j = 0; j < 16; j++) {
                if (sc[j] > -1e29f) {
                    float pj = __expf(sc[j] - mnew);
                    l += pj;
#pragma unroll
                    for (int d4 = 0; d4 < DD; d4 += 4) {
                        float4 vv = *(const float4*)&vs[j][d4];
                        oa[d4]     += pj * vv.x;
                        oa[d4 + 1] += pj * vv.y;
                        oa[d4 + 2] += pj * vv.z;
                        oa[d4 + 3] += pj * vv.w;
                    }
                }
            }
            m = mnew;
        }
    }
    float inv = 1.f / l;
    __half* orow = o + ((long)(b * SS + s_q) * HH + h * DD);
#pragma unroll
    for (int d = 0; d < DD; d += 2)
        *(__half2*)&orow[d] = __floats2half2_rn(oa[d] * inv, oa[d + 1] * inv);
}

// ---------------- global-query attention ----------------
__global__ void __launch_bounds__(128)
glob_attn_kernel(const float* __restrict__ qkv, __half* __restrict__ o)
{
    const int g = blockIdx.x, h = blockIdx.y, b = blockIdx.z;
    const int tid = threadIdx.x;

    __shared__ float qs[DD];
    __shared__ float sc[SS];
    __shared__ float red[4];
    __shared__ float part[2][DD];

    if (tid < DD) qs[tid] = qkv[(long)(b * SS + g) * QKVW + h * DD + tid];
    __syncthreads();

    float lm = -1e30f;
    for (int s = tid; s < SS; s += 128) {
        const float* kr = qkv + ((long)(b * SS + s) * QKVW + HH + h * DD);
        float acc = 0.f;
#pragma unroll
        for (int d4 = 0; d4 < DD; d4 += 4) {
            float4 kk = *(const float4*)&kr[d4];
            acc += qs[d4] * kk.x + qs[d4 + 1] * kk.y + qs[d4 + 2] * kk.z + qs[d4 + 3] * kk.w;
        }
        sc[s] = acc;
        lm = fmaxf(lm, acc);
    }
#pragma unroll
    for (int off = 16; off > 0; off >>= 1)
        lm = fmaxf(lm, __shfl_xor_sync(0xffffffffu, lm, off));
    if ((tid & 31) == 0) red[tid >> 5] = lm;
    __syncthreads();
    float m = fmaxf(fmaxf(red[0], red[1]), fmaxf(red[2], red[3]));

    float ls = 0.f;
    for (int s = tid; s < SS; s += 128) {
        float e = __expf(sc[s] - m);
        sc[s] = e;
        ls += e;
    }
#pragma unroll
    for (int off = 16; off > 0; off >>= 1)
        ls += __shfl_xor_sync(0xffffffffu, ls, off);
    __syncthreads();
    if ((tid & 31) == 0) red[tid >> 5] = ls;
    __syncthreads();
    float l = red[0] + red[1] + red[2] + red[3];

    const int d = tid & 63;
    const int half_ = tid >> 6;
    float acc = 0.f;
    const int s0 = half_ * (SS / 2);
#pragma unroll 4
    for (int s = s0; s < s0 + SS / 2; s++)
        acc += sc[s] * qkv[(long)(b * SS + s) * QKVW + 2 * HH + h * DD + d];
    part[half_][d] = acc;
    __syncthreads();
    if (tid < DD) {
        float inv = 1.f / l;
        o[(long)(b * SS + g) * HH + h * DD + tid] = __float2half((part[0][tid] + part[1][tid]) * inv);
    }
}

// ---------------- pair gather + classifier head ----------------
__global__ void __launch_bounds__(128)
head_kernel(const float* __restrict__ x, const int* __restrict__ pairs,
            const float* __restrict__ Wh, const float* __restrict__ bh,
            float* __restrict__ out)
{
    const int bp = blockIdx.x;
    const int b = bp >> 7;
    const int i = pairs[bp * 2 + 0];
    const int j = pairs[bp * 2 + 1];
    const float* xi = x + (long)(b * SS + i) * HH;
    const float* xj = x + (long)(b * SS + j) * HH;

    float acc[NLC] = {0.f, 0.f, 0.f};
    for (int d = threadIdx.x; d < 2 * HH; d += 128) {
        float e = (d < HH) ? xi[d] : xj[d - HH];
        acc[0] += e * Wh[d * NLC + 0];
        acc[1] += e * Wh[d * NLC + 1];
        acc[2] += e * Wh[d * NLC + 2];
    }
#pragma unroll
    for (int o = 16; o > 0; o >>= 1) {
#pragma unroll
        for (int c = 0; c < NLC; c++)
            acc[c] += __shfl_xor_sync(0xffffffffu, acc[c], o);
    }
    __shared__ float sm[NLC][4];
    int w = threadIdx.x >> 5;
    if ((threadIdx.x & 31) == 0) {
#pragma unroll
        for (int c = 0; c < NLC; c++) sm[c][w] = acc[c];
    }
    __syncthreads();
    if (threadIdx.x < NLC) {
        float s = sm[threadIdx.x][0] + sm[threadIdx.x][1] + sm[threadIdx.x][2] + sm[threadIdx.x][3];
        out[bp * NLC + threadIdx.x] = s + bh[threadIdx.x];
    }
}

// ---------------- host orchestration ----------------
extern "C" void kernel_launch(void* const* d_in, const int* in_sizes, int n_in,
                              void* d_out, int out_size)
{
    const int*   input_ids    = (const int*)  d_in[0];
    const int*   pair_indices = (const int*)  d_in[1];
    const float* emb          = (const float*)d_in[2];
    const float* Wq  = (const float*)d_in[3];
    const float* bq  = (const float*)d_in[4];
    const float* Wk  = (const float*)d_in[5];
    const float* bk  = (const float*)d_in[6];
    const float* Wv  = (const float*)d_in[7];
    const float* bv  = (const float*)d_in[8];
    const float* Wo  = (const float*)d_in[9];
    const float* bo  = (const float*)d_in[10];
    const float* ln1g = (const float*)d_in[11];
    const float* ln1b = (const float*)d_in[12];
    const float* Wf1 = (const float*)d_in[13];
    const float* bf1 = (const float*)d_in[14];
    const float* Wf2 = (const float*)d_in[15];
    const float* bf2 = (const float*)d_in[16];
    const float* ln2g = (const float*)d_in[17];
    const float* ln2b = (const float*)d_in[18];
    const float* Wh  = (const float*)d_in[19];
    const float* bh  = (const float*)d_in[20];
    float* out = (float*)d_out;

    float *x, *qkv, *tb, *bqkv;
    __half *xh, *o16, *h16, *wbuf;
    cudaGetSymbolAddress((void**)&x,    g_x);
    cudaGetSymbolAddress((void**)&qkv,  g_qkv);
    cudaGetSymbolAddress((void**)&tb,   g_t);
    cudaGetSymbolAddress((void**)&bqkv, g_bqkv);
    cudaGetSymbolAddress((void**)&xh,   g_xh);
    cudaGetSymbolAddress((void**)&o16,  g_o16);
    cudaGetSymbolAddress((void**)&h16,  g_h16);
    cudaGetSymbolAddress((void**)&wbuf, g_wbuf);

    // weight conversion / packing (once per call)
    {
        long nQKV = (long)LL * HH * QKVW;  // 7,077,888
        int  nHH  = LL * HH * HH;
        int  nFF  = LL * HH * FF;
        pack_qkv_kernel<<<(int)((nQKV / 8 + 255) / 256), 256>>>(Wq, Wk, Wv, wbuf + WQKVOFF);
        pack_bqkv_kernel<<<(LL * QKVW + 255) / 256, 256>>>(bq, bk, bv, bqkv);
        f2h_kernel<<<(nHH / 8 + 255) / 256, 256>>>(Wo,  wbuf + WOOFF,  nHH);
        f2h_kernel<<<(nFF / 8 + 255) / 256, 256>>>(Wf1, wbuf + WF1OFF, nFF);
        f2h_kernel<<<(nFF / 8 + 255) / 256, 256>>>(Wf2, wbuf + WF2OFF, nFF);
    }

    {
        int total = MROWS * HH;
        embed_kernel<<<(total + 255) / 256, 256>>>(input_ids, emb, x, xh);
    }

    const dim3 gQKV(QKVW / GN, MROWS / GM);   // 18 x 32
    const dim3 gHH (HH   / GN, MROWS / GM);   //  6 x 32
    const dim3 gFF (FF   / GN, MROWS / GM);   // 24 x 32
    const dim3 attnGrid(SS / CW, NHH, BB);
    const dim3 globGrid(GT, NHH, BB);

    for (int l = 0; l < LL; l++) {
        const __half* wqkv = wbuf + WQKVOFF + (long)l * HH * QKVW;
        const __half* wo   = wbuf + WOOFF   + (long)l * HH * HH;
        const __half* w1   = wbuf + WF1OFF  + (long)l * HH * FF;
        const __half* w2   = wbuf + WF2OFF  + (long)l * FF * HH;

        gemm16_kernel<<<gQKV, 256>>>(xh, wqkv, bqkv + l * QKVW, nullptr, qkv, nullptr, MROWS, QKVW, HH, 0);

        band_attn_kernel<<<attnGrid, 128>>>(qkv, o16);
        glob_attn_kernel<<<globGrid, 128>>>(qkv, o16);

        gemm16_kernel<<<gHH, 256>>>(o16, wo, bo + l * HH, x, tb, nullptr, MROWS, HH, HH, 1);
        ln_kernel<<<MROWS, 256>>>(tb, ln1g + l * HH, ln1b + l * HH, x, xh);

        gemm16_kernel<<<gFF, 256>>>(xh, w1, bf1 + l * FF, nullptr, nullptr, h16, MROWS, FF, HH, 2);
        gemm16_kernel<<<gHH, 256>>>(h16, w2, bf2 + l * HH, x, tb, nullptr, MROWS, HH, FF, 1);
        ln_kernel<<<MROWS, 256>>>(tb, ln2g + l * HH, ln2b + l * HH, x, xh);
    }

    head_kernel<<<BB * PP, 128>>>(x, pair_indices, Wh, bh, out);
}

// round 8
// speedup vs baseline: 4.1336x; 1.1801x over previous
#include <cuda_runtime.h>
#include <cuda_fp16.h>
#include <math.h>
#include <stdint.h>

// ---------------- problem constants ----------------
#define BB 2
#define SS 2048
#define HH 768
#define NHH 12
#define DD 64
#define LL 4
#define CW 128
#define GT 16
#define PP 128
#define NLC 3
#define FF (4*HH)
#define MROWS (BB*SS)
#define QKVW (3*HH)   // 2304

// ---------------- scratch ----------------
__device__ float  g_x   [MROWS*HH];
__device__ float  g_qkv [MROWS*QKVW];
__device__ float  g_t   [MROWS*HH];
__device__ __half g_xh  [MROWS*HH];
__device__ __half g_o16 [MROWS*HH];
__device__ __half g_h16 [MROWS*FF];
__device__ float  g_bqkv[LL*QKVW];
// fp16 weights [K][N]: packed QKV (L*768*2304), Wo (L*768*768), Wf1 (L*768*3072), Wf2 (L*3072*768)
#define WQKVOFF 0
#define WOOFF   (3*LL*HH*HH)
#define WF1OFF  (4*LL*HH*HH)
#define WF2OFF  (4*LL*HH*HH + LL*HH*FF)
#define WTOTAL  (4*LL*HH*HH + 2*LL*HH*FF)
__device__ __half g_wbuf[WTOTAL];

// ---------------- fp32 -> fp16 bulk convert ----------------
__global__ void f2h_kernel(const float* __restrict__ s, __half* __restrict__ d, int n)
{
    int i = (blockIdx.x * 256 + threadIdx.x) * 8;
    if (i >= n) return;
    float4 v0 = *(const float4*)&s[i];
    float4 v1 = *(const float4*)&s[i + 4];
    __half2 h0 = __floats2half2_rn(v0.x, v0.y);
    __half2 h1 = __floats2half2_rn(v0.z, v0.w);
    __half2 h2 = __floats2half2_rn(v1.x, v1.y);
    __half2 h3 = __floats2half2_rn(v1.z, v1.w);
    uint4 o;
    o.x = *reinterpret_cast<unsigned*>(&h0);
    o.y = *reinterpret_cast<unsigned*>(&h1);
    o.z = *reinterpret_cast<unsigned*>(&h2);
    o.w = *reinterpret_cast<unsigned*>(&h3);
    *(uint4*)&d[i] = o;
}

// ---------------- pack Wq|Wk|Wv -> [L][H][2304] fp16, scale q by 0.125 ----------------
__global__ void pack_qkv_kernel(const float* __restrict__ Wq, const float* __restrict__ Wk,
                                const float* __restrict__ Wv, __half* __restrict__ dst)
{
    long i = ((long)blockIdx.x * 256 + threadIdx.x) * 8;
    if (i >= (long)LL * HH * QKVW) return;
    int l   = (int)(i / (HH * QKVW));
    int rem = (int)(i - (long)l * HH * QKVW);
    int k   = rem / QKVW;
    int j   = rem - k * QKVW;
    int seg = j / HH;
    int jj  = j - seg * HH;
    const float* src = (seg == 0 ? Wq : seg == 1 ? Wk : Wv) + ((long)l * HH + k) * HH + jj;
    float sc = (seg == 0) ? 0.125f : 1.0f;
    float4 v0 = *(const float4*)&src[0];
    float4 v1 = *(const float4*)&src[4];
    __half2 h0 = __floats2half2_rn(v0.x * sc, v0.y * sc);
    __half2 h1 = __floats2half2_rn(v0.z * sc, v0.w * sc);
    __half2 h2 = __floats2half2_rn(v1.x * sc, v1.y * sc);
    __half2 h3 = __floats2half2_rn(v1.z * sc, v1.w * sc);
    uint4 o;
    o.x = *reinterpret_cast<unsigned*>(&h0);
    o.y = *reinterpret_cast<unsigned*>(&h1);
    o.z = *reinterpret_cast<unsigned*>(&h2);
    o.w = *reinterpret_cast<unsigned*>(&h3);
    *(uint4*)&dst[i] = o;
}

__global__ void pack_bqkv_kernel(const float* __restrict__ bq, const float* __restrict__ bk,
                                 const float* __restrict__ bv, float* __restrict__ dst)
{
    int i = blockIdx.x * 256 + threadIdx.x;
    if (i >= LL * QKVW) return;
    int l = i / QKVW;
    int j = i - l * QKVW;
    int seg = j / HH;
    int jj  = j - seg * HH;
    dst[i] = (seg == 0 ? bq[l * HH + jj] * 0.125f : seg == 1 ? bk[l * HH + jj] : bv[l * HH + jj]);
}

// ---------------- embedding gather ----------------
__global__ void embed_kernel(const int* __restrict__ ids,
                             const float* __restrict__ emb,
                             float* __restrict__ x, __half* __restrict__ xh)
{
    int idx = blockIdx.x * blockDim.x + threadIdx.x;
    if (idx >= MROWS * HH) return;
    int tok = idx / HH;
    int d   = idx - tok * HH;
    float e = emb[(long)ids[tok] * HH + d];
    x[idx]  = e;
    xh[idx] = __float2half(e);
}

// ---------------- fp16 tensor-core GEMM, CTA 128x128, 256 thr, 4-stage cp.async ----------------
// mode 0: Cf = AW+b; mode 1: Cf = AW+b+R; mode 2: Ch = gelu(AW+b)
#define GM 128
#define GN 128
#define NST 4

__device__ __forceinline__ void mma_f16(float* d, const unsigned* a, const unsigned* b) {
    asm volatile(
        "mma.sync.aligned.m16n8k16.row.col.f32.f16.f16.f32 "
        "{%0,%1,%2,%3}, {%4,%5,%6,%7}, {%8,%9}, {%0,%1,%2,%3};\n"
        : "+f"(d[0]), "+f"(d[1]), "+f"(d[2]), "+f"(d[3])
        : "r"(a[0]), "r"(a[1]), "r"(a[2]), "r"(a[3]),
          "r"(b[0]), "r"(b[1]));
}

__device__ __forceinline__ void cp16(unsigned smem, const void* g) {
    asm volatile("cp.async.cg.shared.global [%0], [%1], 16;\n" :: "r"(smem), "l"(g));
}

__global__ void __launch_bounds__(256, 2)
gemm16_kernel(const __half* __restrict__ A, const __half* __restrict__ W,
              const float* __restrict__ bias, const float* __restrict__ R,
              float* __restrict__ Cf, __half* __restrict__ Ch,
              int M, int N, int K, int mode)
{
    // A: [m][pitch12] uint32 (half2 over k); stage = 128*48B = 6KB
    __shared__ unsigned As[NST][GM][12];
    // B: [k][n] fp16, 256B rows, 16B chunks XOR-swizzled by (k&7); stage 4KB
    __shared__ __half Bs[NST][16][GN];

    const int tid  = threadIdx.x;
    const int w    = tid >> 5;
    const int lane = tid & 31;
    const int gid  = lane >> 2;
    const int tig  = lane & 3;
    const int wm   = (w >> 1) * 32;
    const int wn   = (w & 1) * 64;
    const int row0 = blockIdx.y * GM;
    const int col0 = blockIdx.x * GN;

    // A staging: thread -> row tid>>1, k-chunk (tid&1)
    const int ar = tid >> 1;
    const int ac = tid & 1;
    // B staging: thread -> k row tid>>4, n-chunk tid&15 (swizzled)
    const int bk = tid >> 4;
    const int bc = tid & 15;
    const int bcs = bc ^ (bk & 7);

    const unsigned as_base = (unsigned)__cvta_generic_to_shared(&As[0][0][0]);
    const unsigned bs_base = (unsigned)__cvta_generic_to_shared(&Bs[0][0][0]);
    const unsigned a_dst0 = as_base + (ar * 12 + ac * 4) * 4;   // within stage 0
    const unsigned b_dst0 = bs_base + bk * 256 + bcs * 16;

    const long arow_base = (long)(row0 + ar) * K + ac * 8;
    const long brow_col  = (long)col0 + bc * 8;

    // ldmatrix lane addressing
    const int lsel = lane >> 3;
    const int lk   = (lsel & 1) * 8 + (lane & 7);
    const int lnc  = (lsel >> 1);

    float acc[2][8][4];
#pragma unroll
    for (int mt = 0; mt < 2; mt++)
#pragma unroll
        for (int nt = 0; nt < 8; nt++)
#pragma unroll
            for (int u = 0; u < 4; u++) acc[mt][nt][u] = 0.f;

    const int nk = K / 16;

    // stage loader: chunk kt -> ring slot kt&3
    auto load_stage = [&](int kt) {
        const int s = kt & 3;
        cp16(a_dst0 + s * 6144, &A[arow_base + kt * 16]);
        cp16(b_dst0 + s * 4096, &W[(long)(kt * 16 + bk) * N + brow_col]);
        asm volatile("cp.async.commit_group;\n");
    };

    // prologue: 3 stages in flight
    load_stage(0);
    if (nk > 1) load_stage(1); else asm volatile("cp.async.commit_group;\n");
    if (nk > 2) load_stage(2); else asm volatile("cp.async.commit_group;\n");

    for (int kt = 0; kt < nk; kt++) {
        const int s = kt & 3;
        asm volatile("cp.async.wait_group 2;\n" ::: "memory");
        __syncthreads();

        // ALWAYS commit a group so wait_group 2 pins stage kt complete,
        // including the last two iterations (tail fix for R7's race).
        if (kt + 3 < nk) load_stage(kt + 3);
        else asm volatile("cp.async.commit_group;\n");

        unsigned afr[2][4];
#pragma unroll
        for (int mt = 0; mt < 2; mt++) {
            int m = wm + mt * 16 + gid;
            afr[mt][0] = As[s][m    ][tig];
            afr[mt][1] = As[s][m + 8][tig];
            afr[mt][2] = As[s][m    ][tig + 4];
            afr[mt][3] = As[s][m + 8][tig + 4];
        }
        unsigned bfr[8][2];
#pragma unroll
        for (int ntp = 0; ntp < 4; ntp++) {
            int ncg = (wn >> 3) + ntp * 2 + lnc;
            int chunk = ncg ^ (lk & 7);
            unsigned addr = bs_base + s * 4096 + lk * 256 + chunk * 16;
            unsigned r0, r1, r2, r3;
            asm volatile(
                "ldmatrix.sync.aligned.m8n8.x4.trans.shared.b16 {%0,%1,%2,%3}, [%4];"
                : "=r"(r0), "=r"(r1), "=r"(r2), "=r"(r3) : "r"(addr));
            bfr[ntp * 2    ][0] = r0;
            bfr[ntp * 2    ][1] = r1;
            bfr[ntp * 2 + 1][0] = r2;
            bfr[ntp * 2 + 1][1] = r3;
        }
#pragma unroll
        for (int mt = 0; mt < 2; mt++)
#pragma unroll
            for (int nt = 0; nt < 8; nt++)
                mma_f16(acc[mt][nt], afr[mt], bfr[nt]);
    }

    // ---- epilogue ----
#pragma unroll
    for (int nt = 0; nt < 8; nt++) {
        const int cc = col0 + wn + nt * 8 + 2 * tig;
        float2 bv = *(const float2*)&bias[cc];
#pragma unroll
        for (int mt = 0; mt < 2; mt++) {
            int r0 = row0 + wm + mt * 16 + gid;
#pragma unroll
            for (int half_ = 0; half_ < 2; half_++) {
                int rr = r0 + half_ * 8;
                float vx = acc[mt][nt][half_ * 2 + 0] + bv.x;
                float vy = acc[mt][nt][half_ * 2 + 1] + bv.y;
                if (mode == 0) {
                    *(float2*)&Cf[(long)rr * N + cc] = make_float2(vx, vy);
                } else if (mode == 1) {
                    float2 rrv = *(const float2*)&R[(long)rr * N + cc];
                    *(float2*)&Cf[(long)rr * N + cc] = make_float2(vx + rrv.x, vy + rrv.y);
                } else {
                    float t0 = vx, t1 = vy;
                    vx = 0.5f * t0 * (1.f + tanhf(0.7978845608028654f * (t0 + 0.044715f * t0 * t0 * t0)));
                    vy = 0.5f * t1 * (1.f + tanhf(0.7978845608028654f * (t1 + 0.044715f * t1 * t1 * t1)));
                    *(__half2*)&Ch[(long)rr * N + cc] = __floats2half2_rn(vx, vy);
                }
            }
        }
    }
}

// ---------------- layernorm over H=768 ----------------
__global__ void __launch_bounds__(256)
ln_kernel(const float* __restrict__ in, const float* __restrict__ g,
          const float* __restrict__ b, float* __restrict__ out, __half* __restrict__ outh)
{
    const int row = blockIdx.x;
    const float* x = in + (long)row * HH;
    float v0[3];
    float s = 0.f, s2 = 0.f;
#pragma unroll
    for (int i = 0; i < 3; i++) {
        float t = x[threadIdx.x + i * 256];
        v0[i] = t; s += t; s2 += t * t;
    }
#pragma unroll
    for (int o = 16; o > 0; o >>= 1) {
        s  += __shfl_xor_sync(0xffffffffu, s, o);
        s2 += __shfl_xor_sync(0xffffffffu, s2, o);
    }
    __shared__ float red0[8], red1[8];
    int w = threadIdx.x >> 5;
    if ((threadIdx.x & 31) == 0) { red0[w] = s; red1[w] = s2; }
    __syncthreads();
    if (threadIdx.x < 32) {
        s  = (threadIdx.x < 8) ? red0[threadIdx.x] : 0.f;
        s2 = (threadIdx.x < 8) ? red1[threadIdx.x] : 0.f;
#pragma unroll
        for (int o = 4; o > 0; o >>= 1) {
            s  += __shfl_xor_sync(0xffffffffu, s, o);
            s2 += __shfl_xor_sync(0xffffffffu, s2, o);
        }
        if (threadIdx.x == 0) { red0[0] = s; red1[0] = s2; }
    }
    __syncthreads();
    float mean = red0[0] * (1.f / HH);
    float var  = red1[0] * (1.f / HH) - mean * mean;
    float rstd = rsqrtf(var + 1e-5f);
#pragma unroll
    for (int i = 0; i < 3; i++) {
        int c = threadIdx.x + i * 256;
        float val = (v0[i] - mean) * rstd * g[c] + b[c];
        out [(long)row * HH + c] = val;
        outh[(long)row * HH + c] = __float2half(val);
    }
}

// ---------------- banded attention (reads fused qkv, stride QKVW) ----------------
__global__ void __launch_bounds__(128)
band_attn_kernel(const float* __restrict__ qkv, __half* __restrict__ o)
{
    const int n = blockIdx.x, h = blockIdx.y, b = blockIdx.z;
    const int qi = threadIdx.x;
    const int s_q = n * CW + qi;

    const float* qrow = qkv + ((long)(b * SS + s_q) * QKVW + h * DD);
    float qr[DD];
#pragma unroll
    for (int d = 0; d < DD; d++) qr[d] = qrow[d];

    float m = -1e30f, l = 0.f;
    float oa[DD];
#pragma unroll
    for (int d = 0; d < DD; d++) oa[d] = 0.f;

    __shared__ float ks[16][DD];
    __shared__ float vs[16][DD];

    for (int t = 0; t < 25; t++) {
        const bool is_glob = (t == 24);
        const int p0 = is_glob ? 0 : (n * CW - CW + t * 16);
        __syncthreads();
        for (int f = threadIdx.x; f < 256; f += 128) {
            int j  = f >> 4;
            int d4 = (f & 15) * 4;
            int p  = p0 + j;
            int pc = min(max(p, 0), SS - 1);
            long base = (long)(b * SS + pc) * QKVW + h * DD + d4;
            *(float4*)&ks[j][d4] = *(const float4*)&qkv[HH + base];
            *(float4*)&vs[j][d4] = *(const float4*)&qkv[2 * HH + base];
        }
        __syncthreads();

        float sc[16];
        float tmax = -1e30f;
#pragma unroll
        for (int j = 0; j < 16; j++) {
            int p = p0 + j;
            bool valid = is_glob || ((abs(p - s_q) <= CW) && (p >= GT) && (p < SS));
            float s = -1e30f;
            if (valid) {
                s = 0.f;
#pragma unroll
                for (int d4 = 0; d4 < DD; d4 += 4) {
                    float4 kk = *(const float4*)&ks[j][d4];
                    s += qr[d4] * kk.x + qr[d4 + 1] * kk.y + qr[d4 + 2] * kk.z + qr[d4 + 3] * kk.w;
                }
            }
            sc[j] = s;
            tmax = fmaxf(tmax, s);
        }
        if (tmax > -1e29f) {
            float mnew = fmaxf(m, tmax);
            float alpha = __expf(m - mnew);
            l *= alpha;
#pragma unroll
            for (int d = 0; d < DD; d++) oa[d] *= alpha;
#pragma unroll
            for (int j = 0; j < 16; j++) {
                if (sc[j] > -1e29f) {
                    float pj = __expf(sc[j] - mnew);
                    l += pj;
#pragma unroll
                    for (int d4 = 0; d4 < DD; d4 += 4) {
                        float4 vv = *(const float4*)&vs[j][d4];
                        oa[d4]     += pj * vv.x;
                        oa[d4 + 1] += pj * vv.y;
                        oa[d4 + 2] += pj * vv.z;
                        oa[d4 + 3] += pj * vv.w;
                    }
                }
            }
            m = mnew;
        }
    }
    float inv = 1.f / l;
    __half* orow = o + ((long)(b * SS + s_q) * HH + h * DD);
#pragma unroll
    for (int d = 0; d < DD; d += 2)
        *(__half2*)&orow[d] = __floats2half2_rn(oa[d] * inv, oa[d + 1] * inv);
}

// ---------------- global-query attention ----------------
__global__ void __launch_bounds__(128)
glob_attn_kernel(const float* __restrict__ qkv, __half* __restrict__ o)
{
    const int g = blockIdx.x, h = blockIdx.y, b = blockIdx.z;
    const int tid = threadIdx.x;

    __shared__ float qs[DD];
    __shared__ float sc[SS];
    __shared__ float red[4];
    __shared__ float part[2][DD];

    if (tid < DD) qs[tid] = qkv[(long)(b * SS + g) * QKVW + h * DD + tid];
    __syncthreads();

    float lm = -1e30f;
    for (int s = tid; s < SS; s += 128) {
        const float* kr = qkv + ((long)(b * SS + s) * QKVW + HH + h * DD);
        float acc = 0.f;
#pragma unroll
        for (int d4 = 0; d4 < DD; d4 += 4) {
            float4 kk = *(const float4*)&kr[d4];
            acc += qs[d4] * kk.x + qs[d4 + 1] * kk.y + qs[d4 + 2] * kk.z + qs[d4 + 3] * kk.w;
        }
        sc[s] = acc;
        lm = fmaxf(lm, acc);
    }
#pragma unroll
    for (int off = 16; off > 0; off >>= 1)
        lm = fmaxf(lm, __shfl_xor_sync(0xffffffffu, lm, off));
    if ((tid & 31) == 0) red[tid >> 5] = lm;
    __syncthreads();
    float m = fmaxf(fmaxf(red[0], red[1]), fmaxf(red[2], red[3]));

    float ls = 0.f;
    for (int s = tid; s < SS; s += 128) {
        float e = __expf(sc[s] - m);
        sc[s] = e;
        ls += e;
    }
#pragma unroll
    for (int off = 16; off > 0; off >>= 1)
        ls += __shfl_xor_sync(0xffffffffu, ls, off);
    __syncthreads();
    if ((tid & 31) == 0) red[tid >> 5] = ls;
    __syncthreads();
    float l = red[0] + red[1] + red[2] + red[3];

    const int d = tid & 63;
    const int half_ = tid >> 6;
    float acc = 0.f;
    const int s0 = half_ * (SS / 2);
#pragma unroll 4
    for (int s = s0; s < s0 + SS / 2; s++)
        acc += sc[s] * qkv[(long)(b * SS + s) * QKVW + 2 * HH + h * DD + d];
    part[half_][d] = acc;
    __syncthreads();
    if (tid < DD) {
        float inv = 1.f / l;
        o[(long)(b * SS + g) * HH + h * DD + tid] = __float2half((part[0][tid] + part[1][tid]) * inv);
    }
}

// ---------------- pair gather + classifier head ----------------
__global__ void __launch_bounds__(128)
head_kernel(const float* __restrict__ x, const int* __restrict__ pairs,
            const float* __restrict__ Wh, const float* __restrict__ bh,
            float* __restrict__ out)
{
    const int bp = blockIdx.x;
    const int b = bp >> 7;
    const int i = pairs[bp * 2 + 0];
    const int j = pairs[bp * 2 + 1];
    const float* xi = x + (long)(b * SS + i) * HH;
    const float* xj = x + (long)(b * SS + j) * HH;

    float acc[NLC] = {0.f, 0.f, 0.f};
    for (int d = threadIdx.x; d < 2 * HH; d += 128) {
        float e = (d < HH) ? xi[d] : xj[d - HH];
        acc[0] += e * Wh[d * NLC + 0];
        acc[1] += e * Wh[d * NLC + 1];
        acc[2] += e * Wh[d * NLC + 2];
    }
#pragma unroll
    for (int o = 16; o > 0; o >>= 1) {
#pragma unroll
        for (int c = 0; c < NLC; c++)
            acc[c] += __shfl_xor_sync(0xffffffffu, acc[c], o);
    }
    __shared__ float sm[NLC][4];
    int w = threadIdx.x >> 5;
    if ((threadIdx.x & 31) == 0) {
#pragma unroll
        for (int c = 0; c < NLC; c++) sm[c][w] = acc[c];
    }
    __syncthreads();
    if (threadIdx.x < NLC) {
        float s = sm[threadIdx.x][0] + sm[threadIdx.x][1] + sm[threadIdx.x][2] + sm[threadIdx.x][3];
        out[bp * NLC + threadIdx.x] = s + bh[threadIdx.x];
    }
}

// ---------------- host orchestration ----------------
extern "C" void kernel_launch(void* const* d_in, const int* in_sizes, int n_in,
                              void* d_out, int out_size)
{
    const int*   input_ids    = (const int*)  d_in[0];
    const int*   pair_indices = (const int*)  d_in[1];
    const float* emb          = (const float*)d_in[2];
    const float* Wq  = (const float*)d_in[3];
    const float* bq  = (const float*)d_in[4];
    const float* Wk  = (const float*)d_in[5];
    const float* bk  = (const float*)d_in[6];
    const float* Wv  = (const float*)d_in[7];
    const float* bv  = (const float*)d_in[8];
    const float* Wo  = (const float*)d_in[9];
    const float* bo  = (const float*)d_in[10];
    const float* ln1g = (const float*)d_in[11];
    const float* ln1b = (const float*)d_in[12];
    const float* Wf1 = (const float*)d_in[13];
    const float* bf1 = (const float*)d_in[14];
    const float* Wf2 = (const float*)d_in[15];
    const float* bf2 = (const float*)d_in[16];
    const float* ln2g = (const float*)d_in[17];
    const float* ln2b = (const float*)d_in[18];
    const float* Wh  = (const float*)d_in[19];
    const float* bh  = (const float*)d_in[20];
    float* out = (float*)d_out;

    float *x, *qkv, *tb, *bqkv;
    __half *xh, *o16, *h16, *wbuf;
    cudaGetSymbolAddress((void**)&x,    g_x);
    cudaGetSymbolAddress((void**)&qkv,  g_qkv);
    cudaGetSymbolAddress((void**)&tb,   g_t);
    cudaGetSymbolAddress((void**)&bqkv, g_bqkv);
    cudaGetSymbolAddress((void**)&xh,   g_xh);
    cudaGetSymbolAddress((void**)&o16,  g_o16);
    cudaGetSymbolAddress((void**)&h16,  g_h16);
    cudaGetSymbolAddress((void**)&wbuf, g_wbuf);

    // weight conversion / packing (once per call)
    {
        long nQKV = (long)LL * HH * QKVW;
        int  nHH  = LL * HH * HH;
        int  nFF  = LL * HH * FF;
        pack_qkv_kernel<<<(int)((nQKV / 8 + 255) / 256), 256>>>(Wq, Wk, Wv, wbuf + WQKVOFF);
        pack_bqkv_kernel<<<(LL * QKVW + 255) / 256, 256>>>(bq, bk, bv, bqkv);
        f2h_kernel<<<(nHH / 8 + 255) / 256, 256>>>(Wo,  wbuf + WOOFF,  nHH);
        f2h_kernel<<<(nFF / 8 + 255) / 256, 256>>>(Wf1, wbuf + WF1OFF, nFF);
        f2h_kernel<<<(nFF / 8 + 255) / 256, 256>>>(Wf2, wbuf + WF2OFF, nFF);
    }

    {
        int total = MROWS * HH;
        embed_kernel<<<(total + 255) / 256, 256>>>(input_ids, emb, x, xh);
    }

    const dim3 gQKV(QKVW / GN, MROWS / GM);   // 18 x 32
    const dim3 gHH (HH   / GN, MROWS / GM);   //  6 x 32
    const dim3 gFF (FF   / GN, MROWS / GM);   // 24 x 32
    const dim3 attnGrid(SS / CW, NHH, BB);
    const dim3 globGrid(GT, NHH, BB);

    for (int l = 0; l < LL; l++) {
        const __half* wqkv = wbuf + WQKVOFF + (long)l * HH * QKVW;
        const __half* wo   = wbuf + WOOFF   + (long)l * HH * HH;
        const __half* w1   = wbuf + WF1OFF  + (long)l * HH * FF;
        const __half* w2   = wbuf + WF2OFF  + (long)l * FF * HH;

        gemm16_kernel<<<gQKV, 256>>>(xh, wqkv, bqkv + l * QKVW, nullptr, qkv, nullptr, MROWS, QKVW, HH, 0);

        band_attn_kernel<<<attnGrid, 128>>>(qkv, o16);
        glob_attn_kernel<<<globGrid, 128>>>(qkv, o16);

        gemm16_kernel<<<gHH, 256>>>(o16, wo, bo + l * HH, x, tb, nullptr, MROWS, HH, HH, 1);
        ln_kernel<<<MROWS, 256>>>(tb, ln1g + l * HH, ln1b + l * HH, x, xh);

        gemm16_kernel<<<gFF, 256>>>(xh, w1, bf1 + l * FF, nullptr, nullptr, h16, MROWS, FF, HH, 2);
        gemm16_kernel<<<gHH, 256>>>(h16, w2, bf2 + l * HH, x, tb, nullptr, MROWS, HH, FF, 1);
        ln_kernel<<<MROWS, 256>>>(tb, ln2g + l * HH, ln2b + l * HH, x, xh);
    }

    head_kernel<<<BB * PP, 128>>>(x, pair_indices, Wh, bh, out);
}